// round 5
// baseline (speedup 1.0000x reference)
#include <cuda_runtime.h>

#define BB 128
#define TT 152
#define II 75
#define HH 256
#define LL 16
#define CC 625
#define G4 1024
#define EPSV 1e-5f
#define DD 8          // h ring depth (timesteps)
#define GRP 8         // CTAs per layer group
#define NSUB 4        // subtiles per CTA (8 hcols each)

// ---------------- device scratch (no allocation allowed) ----------------
__device__ float d_xseq[(size_t)TT * 256 * BB];        // [t][k256 pad][b]
__device__ float d_hring[(size_t)LL * DD * HH * BB];   // [l][slot][k][b]
__device__ float d_Wir[(size_t)LL * G4 * 256];         // [l][rank][sub][k][32]
__device__ float d_Whr[(size_t)LL * G4 * 256];         // same layout
__device__ unsigned int d_cnt[LL + 1];

__device__ __forceinline__ float sigm(float x) { return 1.f / (1.f + __expf(-x)); }

__device__ __forceinline__ float wsum(float v) {
#pragma unroll
    for (int o = 16; o; o >>= 1) v += __shfl_xor_sync(0xffffffffu, v, o);
    return v;
}

__device__ __forceinline__ unsigned int ld_acq(const unsigned int* p) {
    unsigned int v;
    asm volatile("ld.global.acquire.gpu.u32 %0, [%1];" : "=r"(v) : "l"(p));
    return v;
}
__device__ __forceinline__ void arrive_rel(unsigned int* p) {
    asm volatile("red.release.gpu.global.add.u32 [%0], 1;" :: "l"(p) : "memory");
}
__device__ __forceinline__ void cp16(float* s, const float* g) {
    unsigned int sa = (unsigned int)__cvta_generic_to_shared(s);
    asm volatile("cp.async.cg.shared.global [%0], [%1], 16;" :: "r"(sa), "l"(g));
}
__device__ __forceinline__ void cp_commit() { asm volatile("cp.async.commit_group;"); }
template <int N>
__device__ __forceinline__ void cp_wait() { asm volatile("cp.async.wait_group %0;" :: "n"(N)); }

// packed fp32x2 FMA: d = a*b + d  (2 MACs per issue; ptxas never emits this itself)
__device__ __forceinline__ void ffma2(unsigned long long& d, unsigned long long a,
                                      unsigned long long b) {
    asm("fma.rn.f32x2 %0, %1, %2, %0;" : "+l"(d) : "l"(a), "l"(b));
}

// =====================================================================
// Pre-pass kernels
// =====================================================================
__global__ void prep_reset() {
    int i = threadIdx.x;
    if (i <= LL) d_cnt[i] = (i == 0) ? 0x40000000u : 0u;
}

// sequences [b][t][75] -> d_xseq [t][k(256, zero pad)][b]
__global__ void prep_xseq(const float* __restrict__ seq) {
    __shared__ float tsm[II * 129];
    int t = blockIdx.x, tid = threadIdx.x;
    for (int idx = tid; idx < BB * II; idx += 256) {
        int b = idx / II, k = idx - b * II;
        tsm[k * 129 + b] = seq[(b * TT + t) * II + k];
    }
    __syncthreads();
    float* dst = d_xseq + (size_t)t * (256 * BB);
    for (int idx = tid; idx < 256 * BB; idx += 256) {
        int k = idx >> 7, b = idx & 127;
        dst[idx] = (k < II) ? tsm[k * 129 + b] : 0.f;
    }
}

// Reshape weights into [l][rank][sub(4)][k(256)][32] streaming tiles.
// tile column c32 = hcig*4 + g maps to global col g*256 + rank*32 + sub*8 + hcig.
__global__ void prep_w(const float* __restrict__ Wih0, const float* __restrict__ Wih,
                       const float* __restrict__ Whh) {
    int l = blockIdx.x, rank = blockIdx.y, tid = threadIdx.x;
    size_t dbase = ((size_t)l * GRP + rank) * 32768;
    for (int idx = tid; idx < 32768; idx += 256) {
        int c32 = idx & 31;
        int rest = idx >> 5;
        int k = rest & 255;
        int sub = rest >> 8;
        int g = c32 & 3, hcig = c32 >> 2;
        int col = g * 256 + rank * 32 + sub * 8 + hcig;
        float vi;
        if (l == 0) vi = (k < II) ? Wih0[k * G4 + col] : 0.f;
        else        vi = Wih[((size_t)(l - 1) * HH + k) * G4 + col];
        d_Wir[dbase + idx] = vi;
        d_Whr[dbase + idx] = Whh[((size_t)l * HH + k) * G4 + col];
    }
}

// =====================================================================
// One GEMM phase (f32x2): acc2[8] (16 cols) += src[k][b] * W[k][hcl*16..+15]
// src global [256][128], Wsrc global [256][32]; double-buffered cp.async.
// =====================================================================
__device__ __forceinline__ void gemm_phase(
    unsigned long long* acc2, const float* __restrict__ src,
    const float* __restrict__ Wsrc,
    float* xs0, float* xs1, float* wb0, float* wb1, int tid, int b, int hcl)
{
#pragma unroll
    for (int cc = 0; cc < 2; cc++) {
        float* xd = cc ? xs1 : xs0;
        float* wd = cc ? wb1 : wb0;
#pragma unroll
        for (int i = 0; i < 8; i++) {
            int f = tid + i * 256, kk = f >> 5, bq = f & 31;
            cp16(xd + kk * 132 + bq * 4, src + (cc * 64 + kk) * 128 + bq * 4);
        }
#pragma unroll
        for (int i = 0; i < 2; i++) {
            int f = tid + i * 256, kk = f >> 3, lq = f & 7;
            cp16(wd + kk * 32 + lq * 4, Wsrc + (cc * 64 + kk) * 32 + lq * 4);
        }
        cp_commit();
    }
#pragma unroll
    for (int cc = 0; cc < 4; cc++) {
        if (cc < 3) cp_wait<1>(); else cp_wait<0>();
        __syncthreads();
        const float* xs = (cc & 1) ? xs1 : xs0;
        const float* wb = (cc & 1) ? wb1 : wb0;
#pragma unroll 2
        for (int k = 0; k < 64; k++) {
            float hv = xs[k * 132 + b];
            unsigned int hu = __float_as_uint(hv);
            unsigned long long hv2;
            asm("mov.b64 %0, {%1, %1};" : "=l"(hv2) : "r"(hu));
            const ulonglong2* wr = (const ulonglong2*)(wb + k * 32 + hcl * 16);
#pragma unroll
            for (int i = 0; i < 4; i++) {
                ulonglong2 w = wr[i];
                ffma2(acc2[i * 2 + 0], hv2, w.x);
                ffma2(acc2[i * 2 + 1], hv2, w.y);
            }
        }
        if (cc < 2) {
            __syncthreads();
            int c2 = cc + 2;
            float* xd = (cc & 1) ? xs1 : xs0;
            float* wd = (cc & 1) ? wb1 : wb0;
#pragma unroll
            for (int i = 0; i < 8; i++) {
                int f = tid + i * 256, kk = f >> 5, bq = f & 31;
                cp16(xd + kk * 132 + bq * 4, src + (c2 * 64 + kk) * 128 + bq * 4);
            }
#pragma unroll
            for (int i = 0; i < 2; i++) {
                int f = tid + i * 256, kk = f >> 3, lq = f & 7;
                cp16(wd + kk * 32 + lq * 4, Wsrc + (c2 * 64 + kk) * 32 + lq * 4);
            }
            cp_commit();
        }
    }
    __syncthreads();
}

// =====================================================================
// Wavefront kernel: 16 layer groups x 8 CTAs, all co-resident.
// Group l, rank r owns hcols [r*32, r*32+32); 4 subtiles of 8 hcols.
// =====================================================================
__launch_bounds__(256, 1) __global__ void wave_kernel(
    const float* __restrict__ ghh, const float* __restrict__ bhh,
    const float* __restrict__ gih, const float* __restrict__ bih,
    const float* __restrict__ bias,
    const float* __restrict__ gc,  const float* __restrict__ bc)
{
    extern __shared__ float sm[];
    float* xs0 = sm;                  // 64*132
    float* xs1 = sm + 8448;
    float* wb0 = sm + 16896;          // 64*32
    float* wb1 = sm + 18944;
    float* red = sm + 20992;          // 4*128
    float* ab  = sm + 21504;          // 96

    const int tid = threadIdx.x;
    const int warp = tid >> 5, lane = tid & 31;
    const int b = tid & 127;
    const int hcl = tid >> 7;
    const int l = blockIdx.x >> 3;
    const int rank = blockIdx.x & 7;

    const float* ghh_p = ghh + l * G4;
    const float* bhh_p = bhh + l * G4;
    const float* gih_p = gih + l * G4;
    const float* bih_p = bih + l * G4;
    const float* bias_p = bias + l * G4;
    const float* gc_p = gc + l * HH;
    const float* bc_p = bc + l * HH;

    float cr[16];
#pragma unroll
    for (int i = 0; i < 16; i++) cr[i] = 0.f;

    for (int t = 0; t < TT; t++) {
        if (tid == 0) {
            if (l < LL - 1 && t >= DD)
                while (ld_acq(&d_cnt[l + 2]) < (unsigned)(GRP * (t - DD + 1))) {}
            if (t > 0)
                while (ld_acq(&d_cnt[l + 1]) < (unsigned)(GRP * t)) {}
        }
        __syncthreads();

        const float* xsrc = (l == 0)
            ? d_xseq + (size_t)t * (256 * BB)
            : d_hring + ((size_t)(l - 1) * DD + (t & (DD - 1))) * (HH * BB);
        const float* hsrc = d_hring + ((size_t)l * DD + ((t - 1) & (DD - 1))) * (HH * BB);
        float* hdst = d_hring + ((size_t)l * DD + (t & (DD - 1))) * (HH * BB);

        bool xwaited = (l == 0);

#pragma unroll 1
        for (int sub = 0; sub < NSUB; sub++) {
            unsigned long long aw2[8], ai2[8];
#pragma unroll
            for (int x = 0; x < 8; x++) { aw2[x] = 0ull; ai2[x] = 0ull; }

            const float* whh_p = d_Whr + (((size_t)l * GRP + rank) * NSUB + sub) * 8192;
            const float* wih_p = d_Wir + (((size_t)l * GRP + rank) * NSUB + sub) * 8192;

            if (t > 0)
                gemm_phase(aw2, hsrc, whh_p, xs0, xs1, wb0, wb1, tid, b, hcl);

            if (!xwaited) {
                if (tid == 0)
                    while (ld_acq(&d_cnt[l]) < (unsigned)(GRP * (t + 1))) {}
                __syncthreads();
                xwaited = true;
            }
            gemm_phase(ai2, xsrc, wih_p, xs0, xs1, wb0, wb1, tid, b, hcl);

            // unpack f32x2 accumulators: col layout aw[i*4+g]
            float aw[16], ai[16];
#pragma unroll
            for (int i = 0; i < 8; i++) {
                unsigned int lo, hi;
                asm("mov.b64 {%0, %1}, %2;" : "=r"(lo), "=r"(hi) : "l"(aw2[i]));
                aw[((i >> 1) * 4) + (i & 1) * 2 + 0] = __uint_as_float(lo);
                aw[((i >> 1) * 4) + (i & 1) * 2 + 1] = __uint_as_float(hi);
                asm("mov.b64 {%0, %1}, %2;" : "=r"(lo), "=r"(hi) : "l"(ai2[i]));
                ai[((i >> 1) * 4) + (i & 1) * 2 + 0] = __uint_as_float(lo);
                ai[((i >> 1) * 4) + (i & 1) * 2 + 1] = __uint_as_float(hi);
            }

            // ---- BN stats over batch: 16 cols (wh) + 16 cols (wi) ----
#pragma unroll
            for (int x = 0; x < 16; x++) {
                float s = wsum(aw[x]);
                if (lane == 0) red[0 * 128 + warp * 16 + x] = s;
                float q = wsum(aw[x] * aw[x]);
                if (lane == 0) red[1 * 128 + warp * 16 + x] = q;
                float si = wsum(ai[x]);
                if (lane == 0) red[2 * 128 + warp * 16 + x] = si;
                float qi = wsum(ai[x] * ai[x]);
                if (lane == 0) red[3 * 128 + warp * 16 + x] = qi;
            }
            __syncthreads();
            if (tid < 32) {
                int g = tid & 3, hcig = tid >> 2;
                int w0 = (hcig >> 2) * 4;
                int x = (hcig & 3) * 4 + g;
                float Sh = 0, Qh = 0, Si = 0, Qi = 0;
#pragma unroll
                for (int w = 0; w < 4; w++) {
                    Sh += red[0 * 128 + (w0 + w) * 16 + x];
                    Qh += red[1 * 128 + (w0 + w) * 16 + x];
                    Si += red[2 * 128 + (w0 + w) * 16 + x];
                    Qi += red[3 * 128 + (w0 + w) * 16 + x];
                }
                float mh = Sh * (1.f / 128.f);
                float vh = Qh * (1.f / 128.f) - mh * mh;
                float rsh = rsqrtf(vh + EPSV);
                float mi = Si * (1.f / 128.f);
                float vi = Qi * (1.f / 128.f) - mi * mi;
                float rsi = rsqrtf(vi + EPSV);
                int colg = g * 256 + rank * 32 + sub * 8 + hcig;
                float ah = ghh_p[colg] * rsh;
                float aiC = gih_p[colg] * rsi;
                ab[tid * 3 + 0] = ah;
                ab[tid * 3 + 1] = aiC;
                ab[tid * 3 + 2] = bhh_p[colg] - mh * ah + bih_p[colg] - mi * aiC + bias_p[colg];
            }
            __syncthreads();

            float og[4];
#pragma unroll
            for (int i = 0; i < 4; i++) {
                int lc = (hcl * 4 + i) * 4;
                float s0 = ab[(lc + 0) * 3] * aw[i * 4 + 0] + ab[(lc + 0) * 3 + 1] * ai[i * 4 + 0] + ab[(lc + 0) * 3 + 2];
                float s1 = ab[(lc + 1) * 3] * aw[i * 4 + 1] + ab[(lc + 1) * 3 + 1] * ai[i * 4 + 1] + ab[(lc + 1) * 3 + 2];
                float s2 = ab[(lc + 2) * 3] * aw[i * 4 + 2] + ab[(lc + 2) * 3 + 1] * ai[i * 4 + 2] + ab[(lc + 2) * 3 + 2];
                float s3 = ab[(lc + 3) * 3] * aw[i * 4 + 3] + ab[(lc + 3) * 3 + 1] * ai[i * 4 + 3] + ab[(lc + 3) * 3 + 2];
                float fg = sigm(s0);
                float ig = sigm(s1);
                og[i] = sigm(s2);
                float gg = tanhf(s3);
                cr[sub * 4 + i] = fg * cr[sub * 4 + i] + ig * gg;
            }

            // ---- BN(c) over batch for 8 h cols ----
#pragma unroll
            for (int i = 0; i < 4; i++) {
                float cv = cr[sub * 4 + i];
                float s = wsum(cv);
                float q = wsum(cv * cv);
                if (lane == 0) {
                    red[warp * 8 + i * 2] = s;
                    red[warp * 8 + i * 2 + 1] = q;
                }
            }
            __syncthreads();
            if (tid < 8) {
                int hcig = tid, w0 = (hcig >> 2) * 4;
                float S = 0, Q = 0;
#pragma unroll
                for (int w = 0; w < 4; w++) {
                    S += red[(w0 + w) * 8 + (hcig & 3) * 2];
                    Q += red[(w0 + w) * 8 + (hcig & 3) * 2 + 1];
                }
                float m = S * (1.f / 128.f);
                float v = Q * (1.f / 128.f) - m * m;
                float rs = rsqrtf(v + EPSV);
                int hcolg = rank * 32 + sub * 8 + hcig;
                float ac = gc_p[hcolg] * rs;
                ab[tid * 2] = ac;
                ab[tid * 2 + 1] = bc_p[hcolg] - m * ac;
            }
            __syncthreads();

            float* hout = hdst + (rank * 32 + sub * 8) * BB;
#pragma unroll
            for (int i = 0; i < 4; i++) {
                int hc = hcl * 4 + i;
                float cn = ab[hc * 2] * cr[sub * 4 + i] + ab[hc * 2 + 1];
                hout[hc * BB + b] = og[i] * tanhf(cn);
            }
            __syncthreads();
        }

        __threadfence();
        __syncthreads();
        if (tid == 0) arrive_rel(&d_cnt[l + 1]);
    }
}

// =====================================================================
// Final: out = softmax(h15(T-1) @ W_lin + b_lin). grid 128 (batch), block 256.
// =====================================================================
__launch_bounds__(256) __global__ void final_kernel(
    const float* __restrict__ Wlin, const float* __restrict__ blin,
    float* __restrict__ out)
{
    __shared__ float xr[256];
    __shared__ float lg[CC];
    __shared__ float rbuf[8];
    const float* hs = d_hring + ((size_t)(LL - 1) * DD + ((TT - 1) & (DD - 1))) * (HH * BB);
    int tid = threadIdx.x, warp = tid >> 5, lane = tid & 31;

    xr[tid] = hs[tid * BB + blockIdx.x];
    __syncthreads();

    float lmax = -1e30f;
    for (int cidx = tid; cidx < CC; cidx += 256) {
        float a = blin[cidx];
#pragma unroll 4
        for (int k = 0; k < 256; k++) a += xr[k] * Wlin[k * CC + cidx];
        lg[cidx] = a;
        lmax = fmaxf(lmax, a);
    }
#pragma unroll
    for (int o = 16; o; o >>= 1) lmax = fmaxf(lmax, __shfl_xor_sync(0xffffffffu, lmax, o));
    if (lane == 0) rbuf[warp] = lmax;
    __syncthreads();
    float M = rbuf[0];
#pragma unroll
    for (int w = 1; w < 8; w++) M = fmaxf(M, rbuf[w]);
    __syncthreads();

    float lsum = 0.f;
    for (int cidx = tid; cidx < CC; cidx += 256) {
        float e = __expf(lg[cidx] - M);
        lg[cidx] = e;
        lsum += e;
    }
#pragma unroll
    for (int o = 16; o; o >>= 1) lsum += __shfl_xor_sync(0xffffffffu, lsum, o);
    if (lane == 0) rbuf[warp] = lsum;
    __syncthreads();
    float S = 0.f;
#pragma unroll
    for (int w = 0; w < 8; w++) S += rbuf[w];
    float inv = 1.f / S;
    for (int cidx = tid; cidx < CC; cidx += 256)
        out[blockIdx.x * CC + cidx] = lg[cidx] * inv;
}

// =====================================================================
extern "C" void kernel_launch(void* const* d_in, const int* in_sizes, int n_in,
                              void* d_out, int out_size)
{
    const float* seq  = (const float*)d_in[0];
    const float* Wih0 = (const float*)d_in[1];
    const float* Wih  = (const float*)d_in[2];
    const float* Whh  = (const float*)d_in[3];
    const float* bias = (const float*)d_in[4];
    const float* gih  = (const float*)d_in[5];
    const float* bih  = (const float*)d_in[6];
    const float* ghh  = (const float*)d_in[7];
    const float* bhh  = (const float*)d_in[8];
    const float* gc   = (const float*)d_in[9];
    const float* bc   = (const float*)d_in[10];
    const float* Wlin = (const float*)d_in[11];
    const float* blin = (const float*)d_in[12];
    float* out = (float*)d_out;

    const int SMEM_WAVE = 122880;   // ~86.4KB used; padded to keep 1 CTA/SM

    cudaFuncSetAttribute((const void*)wave_kernel,
                         cudaFuncAttributeMaxDynamicSharedMemorySize, SMEM_WAVE);

    prep_reset<<<1, 32>>>();
    prep_xseq<<<TT, 256>>>(seq);
    prep_w<<<dim3(LL, GRP), 256>>>(Wih0, Wih, Whh);
    wave_kernel<<<LL * GRP, 256, SMEM_WAVE>>>(ghh, bhh, gih, bih, bias, gc, bc);
    final_kernel<<<BB, 256>>>(Wlin, blin, out);
}

// round 6
// speedup vs baseline: 1.0011x; 1.0011x over previous
#include <cuda_runtime.h>

#define BB 128
#define TT 152
#define II 75
#define HH 256
#define LL 16
#define CC 625
#define G4 1024
#define EPSV 1e-5f
#define DD 8          // h ring depth (timesteps)
#define GRP 8         // CTAs per layer group
#define NSUB 4        // subtiles per CTA (8 hcols each)

// ---------------- device scratch (no allocation allowed) ----------------
__device__ float d_xseq[(size_t)TT * 256 * BB];        // [t][k256 pad][b]
__device__ float d_hring[(size_t)LL * DD * HH * BB];   // [l][slot][k][b]
__device__ float d_Wir[(size_t)LL * G4 * 256];         // [l][rank][sub][k][32]
__device__ float d_Whr[(size_t)LL * G4 * 256];         // same layout
__device__ unsigned int d_cnt[LL + 1];

__device__ __forceinline__ float sigm(float x) { return 1.f / (1.f + __expf(-x)); }

__device__ __forceinline__ float wsum(float v) {
#pragma unroll
    for (int o = 16; o; o >>= 1) v += __shfl_xor_sync(0xffffffffu, v, o);
    return v;
}

__device__ __forceinline__ unsigned int ld_acq(const unsigned int* p) {
    unsigned int v;
    asm volatile("ld.global.acquire.gpu.u32 %0, [%1];" : "=r"(v) : "l"(p));
    return v;
}
__device__ __forceinline__ void arrive_rel(unsigned int* p) {
    asm volatile("red.release.gpu.global.add.u32 [%0], 1;" :: "l"(p) : "memory");
}
__device__ __forceinline__ void cp16(float* s, const float* g) {
    unsigned int sa = (unsigned int)__cvta_generic_to_shared(s);
    asm volatile("cp.async.cg.shared.global [%0], [%1], 16;" :: "r"(sa), "l"(g));
}
__device__ __forceinline__ void cp_commit() { asm volatile("cp.async.commit_group;"); }
template <int N>
__device__ __forceinline__ void cp_wait() { asm volatile("cp.async.wait_group %0;" :: "n"(N)); }

// packed fp32x2 FMA: d = a*b + d  (2 MACs per issue; ptxas never emits this itself)
__device__ __forceinline__ void ffma2(unsigned long long& d, unsigned long long a,
                                      unsigned long long b) {
    asm("fma.rn.f32x2 %0, %1, %2, %0;" : "+l"(d) : "l"(a), "l"(b));
}

// =====================================================================
// Pre-pass kernels
// =====================================================================
__global__ void prep_reset() {
    int i = threadIdx.x;
    if (i <= LL) d_cnt[i] = (i == 0) ? 0x40000000u : 0u;
}

// sequences [b][t][75] -> d_xseq [t][k(256, zero pad)][b]
__global__ void prep_xseq(const float* __restrict__ seq) {
    __shared__ float tsm[II * 129];
    int t = blockIdx.x, tid = threadIdx.x;
    for (int idx = tid; idx < BB * II; idx += 256) {
        int b = idx / II, k = idx - b * II;
        tsm[k * 129 + b] = seq[(b * TT + t) * II + k];
    }
    __syncthreads();
    float* dst = d_xseq + (size_t)t * (256 * BB);
    for (int idx = tid; idx < 256 * BB; idx += 256) {
        int k = idx >> 7, b = idx & 127;
        dst[idx] = (k < II) ? tsm[k * 129 + b] : 0.f;
    }
}

// Reshape weights into [l][rank][sub(4)][k(256)][32] streaming tiles.
// tile column c32 = hcig*4 + g maps to global col g*256 + rank*32 + sub*8 + hcig.
__global__ void prep_w(const float* __restrict__ Wih0, const float* __restrict__ Wih,
                       const float* __restrict__ Whh) {
    int l = blockIdx.x, rank = blockIdx.y, tid = threadIdx.x;
    size_t dbase = ((size_t)l * GRP + rank) * 32768;
    for (int idx = tid; idx < 32768; idx += 256) {
        int c32 = idx & 31;
        int rest = idx >> 5;
        int k = rest & 255;
        int sub = rest >> 8;
        int g = c32 & 3, hcig = c32 >> 2;
        int col = g * 256 + rank * 32 + sub * 8 + hcig;
        float vi;
        if (l == 0) vi = (k < II) ? Wih0[k * G4 + col] : 0.f;
        else        vi = Wih[((size_t)(l - 1) * HH + k) * G4 + col];
        d_Wir[dbase + idx] = vi;
        d_Whr[dbase + idx] = Whh[((size_t)l * HH + k) * G4 + col];
    }
}

// =====================================================================
// One GEMM phase (f32x2): acc2[8] (16 cols) += src[k][b] * W[k][hcl*16..+15]
// src global [256][128], Wsrc global [256][32]; double-buffered cp.async.
// =====================================================================
__device__ __forceinline__ void gemm_phase(
    unsigned long long* acc2, const float* __restrict__ src,
    const float* __restrict__ Wsrc,
    float* xs0, float* xs1, float* wb0, float* wb1, int tid, int b, int hcl)
{
#pragma unroll
    for (int cc = 0; cc < 2; cc++) {
        float* xd = cc ? xs1 : xs0;
        float* wd = cc ? wb1 : wb0;
#pragma unroll
        for (int i = 0; i < 8; i++) {
            int f = tid + i * 256, kk = f >> 5, bq = f & 31;
            cp16(xd + kk * 132 + bq * 4, src + (cc * 64 + kk) * 128 + bq * 4);
        }
#pragma unroll
        for (int i = 0; i < 2; i++) {
            int f = tid + i * 256, kk = f >> 3, lq = f & 7;
            cp16(wd + kk * 32 + lq * 4, Wsrc + (cc * 64 + kk) * 32 + lq * 4);
        }
        cp_commit();
    }
#pragma unroll
    for (int cc = 0; cc < 4; cc++) {
        if (cc < 3) cp_wait<1>(); else cp_wait<0>();
        __syncthreads();
        const float* xs = (cc & 1) ? xs1 : xs0;
        const float* wb = (cc & 1) ? wb1 : wb0;
#pragma unroll 2
        for (int k = 0; k < 64; k++) {
            float hv = xs[k * 132 + b];
            unsigned int hu = __float_as_uint(hv);
            unsigned long long hv2;
            asm("mov.b64 %0, {%1, %1};" : "=l"(hv2) : "r"(hu));
            const ulonglong2* wr = (const ulonglong2*)(wb + k * 32 + hcl * 16);
#pragma unroll
            for (int i = 0; i < 4; i++) {
                ulonglong2 w = wr[i];
                ffma2(acc2[i * 2 + 0], hv2, w.x);
                ffma2(acc2[i * 2 + 1], hv2, w.y);
            }
        }
        if (cc < 2) {
            __syncthreads();
            int c2 = cc + 2;
            float* xd = (cc & 1) ? xs1 : xs0;
            float* wd = (cc & 1) ? wb1 : wb0;
#pragma unroll
            for (int i = 0; i < 8; i++) {
                int f = tid + i * 256, kk = f >> 5, bq = f & 31;
                cp16(xd + kk * 132 + bq * 4, src + (c2 * 64 + kk) * 128 + bq * 4);
            }
#pragma unroll
            for (int i = 0; i < 2; i++) {
                int f = tid + i * 256, kk = f >> 3, lq = f & 7;
                cp16(wd + kk * 32 + lq * 4, Wsrc + (c2 * 64 + kk) * 32 + lq * 4);
            }
            cp_commit();
        }
    }
    __syncthreads();
}

// =====================================================================
// Wavefront kernel: 16 layer groups x 8 CTAs, all co-resident.
// Group l, rank r owns hcols [r*32, r*32+32); 4 subtiles of 8 hcols.
// =====================================================================
__launch_bounds__(256, 1) __global__ void wave_kernel(
    const float* __restrict__ ghh, const float* __restrict__ bhh,
    const float* __restrict__ gih, const float* __restrict__ bih,
    const float* __restrict__ bias,
    const float* __restrict__ gc,  const float* __restrict__ bc)
{
    extern __shared__ float sm[];
    float* xs0 = sm;                  // 64*132
    float* xs1 = sm + 8448;
    float* wb0 = sm + 16896;          // 64*32
    float* wb1 = sm + 18944;
    float* red = sm + 20992;          // 4*128
    float* ab  = sm + 21504;          // 96

    const int tid = threadIdx.x;
    const int warp = tid >> 5, lane = tid & 31;
    const int b = tid & 127;
    const int hcl = tid >> 7;
    const int l = blockIdx.x >> 3;
    const int rank = blockIdx.x & 7;

    const float* ghh_p = ghh + l * G4;
    const float* bhh_p = bhh + l * G4;
    const float* gih_p = gih + l * G4;
    const float* bih_p = bih + l * G4;
    const float* bias_p = bias + l * G4;
    const float* gc_p = gc + l * HH;
    const float* bc_p = bc + l * HH;

    float cr[16];
#pragma unroll
    for (int i = 0; i < 16; i++) cr[i] = 0.f;

    for (int t = 0; t < TT; t++) {
        if (tid == 0) {
            if (l < LL - 1 && t >= DD)
                while (ld_acq(&d_cnt[l + 2]) < (unsigned)(GRP * (t - DD + 1))) {}
            if (t > 0)
                while (ld_acq(&d_cnt[l + 1]) < (unsigned)(GRP * t)) {}
        }
        __syncthreads();

        const float* xsrc = (l == 0)
            ? d_xseq + (size_t)t * (256 * BB)
            : d_hring + ((size_t)(l - 1) * DD + (t & (DD - 1))) * (HH * BB);
        const float* hsrc = d_hring + ((size_t)l * DD + ((t - 1) & (DD - 1))) * (HH * BB);
        float* hdst = d_hring + ((size_t)l * DD + (t & (DD - 1))) * (HH * BB);

        bool xwaited = (l == 0);

#pragma unroll 1
        for (int sub = 0; sub < NSUB; sub++) {
            unsigned long long aw2[8], ai2[8];
#pragma unroll
            for (int x = 0; x < 8; x++) { aw2[x] = 0ull; ai2[x] = 0ull; }

            const float* whh_p = d_Whr + (((size_t)l * GRP + rank) * NSUB + sub) * 8192;
            const float* wih_p = d_Wir + (((size_t)l * GRP + rank) * NSUB + sub) * 8192;

            if (t > 0)
                gemm_phase(aw2, hsrc, whh_p, xs0, xs1, wb0, wb1, tid, b, hcl);

            if (!xwaited) {
                if (tid == 0)
                    while (ld_acq(&d_cnt[l]) < (unsigned)(GRP * (t + 1))) {}
                __syncthreads();
                xwaited = true;
            }
            gemm_phase(ai2, xsrc, wih_p, xs0, xs1, wb0, wb1, tid, b, hcl);

            // unpack f32x2 accumulators: col layout aw[i*4+g]
            float aw[16], ai[16];
#pragma unroll
            for (int i = 0; i < 8; i++) {
                unsigned int lo, hi;
                asm("mov.b64 {%0, %1}, %2;" : "=r"(lo), "=r"(hi) : "l"(aw2[i]));
                aw[((i >> 1) * 4) + (i & 1) * 2 + 0] = __uint_as_float(lo);
                aw[((i >> 1) * 4) + (i & 1) * 2 + 1] = __uint_as_float(hi);
                asm("mov.b64 {%0, %1}, %2;" : "=r"(lo), "=r"(hi) : "l"(ai2[i]));
                ai[((i >> 1) * 4) + (i & 1) * 2 + 0] = __uint_as_float(lo);
                ai[((i >> 1) * 4) + (i & 1) * 2 + 1] = __uint_as_float(hi);
            }

            // ---- BN stats over batch: 16 cols (wh) + 16 cols (wi) ----
#pragma unroll
            for (int x = 0; x < 16; x++) {
                float s = wsum(aw[x]);
                if (lane == 0) red[0 * 128 + warp * 16 + x] = s;
                float q = wsum(aw[x] * aw[x]);
                if (lane == 0) red[1 * 128 + warp * 16 + x] = q;
                float si = wsum(ai[x]);
                if (lane == 0) red[2 * 128 + warp * 16 + x] = si;
                float qi = wsum(ai[x] * ai[x]);
                if (lane == 0) red[3 * 128 + warp * 16 + x] = qi;
            }
            __syncthreads();
            if (tid < 32) {
                int g = tid & 3, hcig = tid >> 2;
                int w0 = (hcig >> 2) * 4;
                int x = (hcig & 3) * 4 + g;
                float Sh = 0, Qh = 0, Si = 0, Qi = 0;
#pragma unroll
                for (int w = 0; w < 4; w++) {
                    Sh += red[0 * 128 + (w0 + w) * 16 + x];
                    Qh += red[1 * 128 + (w0 + w) * 16 + x];
                    Si += red[2 * 128 + (w0 + w) * 16 + x];
                    Qi += red[3 * 128 + (w0 + w) * 16 + x];
                }
                float mh = Sh * (1.f / 128.f);
                float vh = Qh * (1.f / 128.f) - mh * mh;
                float rsh = rsqrtf(vh + EPSV);
                float mi = Si * (1.f / 128.f);
                float vi = Qi * (1.f / 128.f) - mi * mi;
                float rsi = rsqrtf(vi + EPSV);
                int colg = g * 256 + rank * 32 + sub * 8 + hcig;
                float ah = ghh_p[colg] * rsh;
                float aiC = gih_p[colg] * rsi;
                ab[tid * 3 + 0] = ah;
                ab[tid * 3 + 1] = aiC;
                ab[tid * 3 + 2] = bhh_p[colg] - mh * ah + bih_p[colg] - mi * aiC + bias_p[colg];
            }
            __syncthreads();

            float og[4];
#pragma unroll
            for (int i = 0; i < 4; i++) {
                int lc = (hcl * 4 + i) * 4;
                float s0 = ab[(lc + 0) * 3] * aw[i * 4 + 0] + ab[(lc + 0) * 3 + 1] * ai[i * 4 + 0] + ab[(lc + 0) * 3 + 2];
                float s1 = ab[(lc + 1) * 3] * aw[i * 4 + 1] + ab[(lc + 1) * 3 + 1] * ai[i * 4 + 1] + ab[(lc + 1) * 3 + 2];
                float s2 = ab[(lc + 2) * 3] * aw[i * 4 + 2] + ab[(lc + 2) * 3 + 1] * ai[i * 4 + 2] + ab[(lc + 2) * 3 + 2];
                float s3 = ab[(lc + 3) * 3] * aw[i * 4 + 3] + ab[(lc + 3) * 3 + 1] * ai[i * 4 + 3] + ab[(lc + 3) * 3 + 2];
                float fg = sigm(s0);
                float ig = sigm(s1);
                og[i] = sigm(s2);
                float gg = tanhf(s3);
                cr[sub * 4 + i] = fg * cr[sub * 4 + i] + ig * gg;
            }

            // ---- BN(c) over batch for 8 h cols ----
#pragma unroll
            for (int i = 0; i < 4; i++) {
                float cv = cr[sub * 4 + i];
                float s = wsum(cv);
                float q = wsum(cv * cv);
                if (lane == 0) {
                    red[warp * 8 + i * 2] = s;
                    red[warp * 8 + i * 2 + 1] = q;
                }
            }
            __syncthreads();
            if (tid < 8) {
                int hcig = tid, w0 = (hcig >> 2) * 4;
                float S = 0, Q = 0;
#pragma unroll
                for (int w = 0; w < 4; w++) {
                    S += red[(w0 + w) * 8 + (hcig & 3) * 2];
                    Q += red[(w0 + w) * 8 + (hcig & 3) * 2 + 1];
                }
                float m = S * (1.f / 128.f);
                float v = Q * (1.f / 128.f) - m * m;
                float rs = rsqrtf(v + EPSV);
                int hcolg = rank * 32 + sub * 8 + hcig;
                float ac = gc_p[hcolg] * rs;
                ab[tid * 2] = ac;
                ab[tid * 2 + 1] = bc_p[hcolg] - m * ac;
            }
            __syncthreads();

            float* hout = hdst + (rank * 32 + sub * 8) * BB;
#pragma unroll
            for (int i = 0; i < 4; i++) {
                int hc = hcl * 4 + i;
                float cn = ab[hc * 2] * cr[sub * 4 + i] + ab[hc * 2 + 1];
                hout[hc * BB + b] = og[i] * tanhf(cn);
            }
            __syncthreads();
        }

        __threadfence();
        __syncthreads();
        if (tid == 0) arrive_rel(&d_cnt[l + 1]);
    }
}

// =====================================================================
// Final: out = softmax(h15(T-1) @ W_lin + b_lin). grid 128 (batch), block 256.
// =====================================================================
__launch_bounds__(256) __global__ void final_kernel(
    const float* __restrict__ Wlin, const float* __restrict__ blin,
    float* __restrict__ out)
{
    __shared__ float xr[256];
    __shared__ float lg[CC];
    __shared__ float rbuf[8];
    const float* hs = d_hring + ((size_t)(LL - 1) * DD + ((TT - 1) & (DD - 1))) * (HH * BB);
    int tid = threadIdx.x, warp = tid >> 5, lane = tid & 31;

    xr[tid] = hs[tid * BB + blockIdx.x];
    __syncthreads();

    float lmax = -1e30f;
    for (int cidx = tid; cidx < CC; cidx += 256) {
        float a = blin[cidx];
#pragma unroll 4
        for (int k = 0; k < 256; k++) a += xr[k] * Wlin[k * CC + cidx];
        lg[cidx] = a;
        lmax = fmaxf(lmax, a);
    }
#pragma unroll
    for (int o = 16; o; o >>= 1) lmax = fmaxf(lmax, __shfl_xor_sync(0xffffffffu, lmax, o));
    if (lane == 0) rbuf[warp] = lmax;
    __syncthreads();
    float M = rbuf[0];
#pragma unroll
    for (int w = 1; w < 8; w++) M = fmaxf(M, rbuf[w]);
    __syncthreads();

    float lsum = 0.f;
    for (int cidx = tid; cidx < CC; cidx += 256) {
        float e = __expf(lg[cidx] - M);
        lg[cidx] = e;
        lsum += e;
    }
#pragma unroll
    for (int o = 16; o; o >>= 1) lsum += __shfl_xor_sync(0xffffffffu, lsum, o);
    if (lane == 0) rbuf[warp] = lsum;
    __syncthreads();
    float S = 0.f;
#pragma unroll
    for (int w = 0; w < 8; w++) S += rbuf[w];
    float inv = 1.f / S;
    for (int cidx = tid; cidx < CC; cidx += 256)
        out[blockIdx.x * CC + cidx] = lg[cidx] * inv;
}

// =====================================================================
extern "C" void kernel_launch(void* const* d_in, const int* in_sizes, int n_in,
                              void* d_out, int out_size)
{
    const float* seq  = (const float*)d_in[0];
    const float* Wih0 = (const float*)d_in[1];
    const float* Wih  = (const float*)d_in[2];
    const float* Whh  = (const float*)d_in[3];
    const float* bias = (const float*)d_in[4];
    const float* gih  = (const float*)d_in[5];
    const float* bih  = (const float*)d_in[6];
    const float* ghh  = (const float*)d_in[7];
    const float* bhh  = (const float*)d_in[8];
    const float* gc   = (const float*)d_in[9];
    const float* bc   = (const float*)d_in[10];
    const float* Wlin = (const float*)d_in[11];
    const float* blin = (const float*)d_in[12];
    float* out = (float*)d_out;

    const int SMEM_WAVE = 122880;   // ~86.4KB used; padded to keep 1 CTA/SM

    cudaFuncSetAttribute((const void*)wave_kernel,
                         cudaFuncAttributeMaxDynamicSharedMemorySize, SMEM_WAVE);

    prep_reset<<<1, 32>>>();
    prep_xseq<<<TT, 256>>>(seq);
    prep_w<<<dim3(LL, GRP), 256>>>(Wih0, Wih, Whh);
    wave_kernel<<<LL * GRP, 256, SMEM_WAVE>>>(ghh, bhh, gih, bih, bias, gc, bc);
    final_kernel<<<BB, 256>>>(Wlin, blin, out);
}

// round 10
// speedup vs baseline: 1.7784x; 1.7764x over previous
#include <cuda_runtime.h>
#include <cuda_bf16.h>

#define BB 128
#define TT 152
#define II 75
#define HH 256
#define LL 16
#define CC 625
#define G4 1024
#define EPSV 1e-5f
#define DD 8
#define GRP 8

// ---------------- device scratch (no allocation allowed) ----------------
// Weights per (l,rank): 256KB = [wi_hi | wi_lo | wh_hi | wh_lo], each 64KB
// section layout (A-fragment direct): [kblk16][warpM8][lane32][16B]
__device__ __align__(128) __nv_bfloat16 d_WA[(size_t)LL * GRP * 131072];
// x / h images (B-fragment direct): per t/slot 128KB = [part2][kblk16][nblk16][lane32][8B]
__device__ __align__(128) __nv_bfloat16 d_xB[(size_t)TT * 65536];
__device__ __align__(128) __nv_bfloat16 d_hB[(size_t)LL * DD * 65536];
__device__ unsigned int d_cnt[LL + 1];

__device__ __forceinline__ float sigm(float x) { return 1.f / (1.f + __expf(-x)); }

__device__ __forceinline__ unsigned int ld_acq(const unsigned int* p) {
    unsigned int v;
    asm volatile("ld.global.acquire.gpu.u32 %0, [%1];" : "=r"(v) : "l"(p));
    return v;
}
__device__ __forceinline__ void arrive_rel(unsigned int* p) {
    asm volatile("red.release.gpu.global.add.u32 [%0], 1;" :: "l"(p) : "memory");
}
__device__ __forceinline__ void cp16(unsigned int sa, const void* g) {
    asm volatile("cp.async.cg.shared.global [%0], [%1], 16;" :: "r"(sa), "l"(g));
}
__device__ __forceinline__ void cp_commit() { asm volatile("cp.async.commit_group;"); }
template <int N>
__device__ __forceinline__ void cp_wait() { asm volatile("cp.async.wait_group %0;" :: "n"(N)); }

__device__ __forceinline__ unsigned int smem_u32(const void* p) {
    unsigned int a;
    asm("{ .reg .u64 t; cvta.to.shared.u64 t, %1; cvt.u32.u64 %0, t; }" : "=r"(a) : "l"(p));
    return a;
}

// classic warp MMA: D(m16n8 f32) += A(m16k16 bf16,row) * B(k16n8 bf16,col)
__device__ __forceinline__ void mma16816(float* d, const unsigned* a, const unsigned* b) {
    asm volatile(
        "mma.sync.aligned.m16n8k16.row.col.f32.bf16.bf16.f32 "
        "{%0,%1,%2,%3}, {%4,%5,%6,%7}, {%8,%9}, {%0,%1,%2,%3};"
        : "+f"(d[0]), "+f"(d[1]), "+f"(d[2]), "+f"(d[3])
        : "r"(a[0]), "r"(a[1]), "r"(a[2]), "r"(a[3]), "r"(b[0]), "r"(b[1]));
}

// ================= pre-pass =================
__global__ void prep_reset() {
    int i = threadIdx.x;
    if (i <= LL) d_cnt[i] = (i == 0) ? 0x40000000u : 0u;
}

// B-fragment byte offset for element (k, b) within one 64KB part image
__host__ __device__ __forceinline__ int boff(int k, int b) {
    return (((k >> 4) * 16 + (b >> 3)) * 32 + (b & 7) * 4 + ((k & 7) >> 1)) * 8
           + ((k >> 3) & 1) * 4 + (k & 1) * 2;
}
// A-fragment byte offset for element (j, k) within one 64KB section
__device__ __forceinline__ int aoff(int j, int k) {
    return (((k >> 4) * 8 + (j >> 4)) * 32 + (j & 7) * 4 + ((k & 7) >> 1)) * 16
           + (((j >> 3) & 1) + 2 * ((k >> 3) & 1)) * 4 + (k & 1) * 2;
}

__global__ void prep_xseq(const float* __restrict__ seq) {
    int t = blockIdx.x, tid = threadIdx.x;
    char* base = (char*)(d_xB + (size_t)t * 65536);
    for (int idx = tid; idx < 32768; idx += 256) {
        int b = idx >> 8, k = idx & 255;
        float v = (k < II) ? seq[(b * TT + t) * II + k] : 0.f;
        __nv_bfloat16 hi = __float2bfloat16(v);
        __nv_bfloat16 lo = __float2bfloat16(v - __bfloat162float(hi));
        int off = boff(k, b);
        *(__nv_bfloat16*)(base + off) = hi;
        *(__nv_bfloat16*)(base + 65536 + off) = lo;
    }
}

__global__ void prep_w(const float* __restrict__ Wih0, const float* __restrict__ Wih,
                       const float* __restrict__ Whh) {
    int l = blockIdx.x, rank = blockIdx.y, tid = threadIdx.x;
    char* base = (char*)d_WA + (size_t)(l * GRP + rank) * 262144;
    for (int idx = tid; idx < 32768; idx += 256) {
        int j = idx >> 8, k = idx & 255;
        int col = ((j & 3) << 8) + rank * 32 + (j >> 2);
        float vi;
        if (l == 0) vi = (k < II) ? Wih0[k * G4 + col] : 0.f;
        else        vi = Wih[((size_t)(l - 1) * HH + k) * G4 + col];
        float vh = Whh[((size_t)l * HH + k) * G4 + col];
        int off = aoff(j, k);
        __nv_bfloat16 h1 = __float2bfloat16(vi);
        *(__nv_bfloat16*)(base + off) = h1;
        *(__nv_bfloat16*)(base + 65536 + off) = __float2bfloat16(vi - __bfloat162float(h1));
        __nv_bfloat16 h2 = __float2bfloat16(vh);
        *(__nv_bfloat16*)(base + 131072 + off) = h2;
        *(__nv_bfloat16*)(base + 196608 + off) = __float2bfloat16(vh - __bfloat162float(h2));
    }
}

// ================= wavefront kernel =================
#define P_WI 0
#define P_WH 65536
#define P_STR 131072
#define STRB 24576
#define P_SG 180224
#define SMEM_TOT 214016

__launch_bounds__(256, 1) __global__ void wave_kernel(
    const float* __restrict__ gih, const float* __restrict__ bih,
    const float* __restrict__ ghh, const float* __restrict__ bhh,
    const float* __restrict__ bias,
    const float* __restrict__ gc,  const float* __restrict__ bc)
{
    extern __shared__ char sm[];
    const unsigned int smb = smem_u32(sm);
    const int tid = threadIdx.x, lane = tid & 31, w = tid >> 5;
    const int l = blockIdx.x >> 3, rank = blockIdx.x & 7;

    const char* wab = (const char*)d_WA + (size_t)(l * GRP + rank) * 262144;
    // persistent hi-part weights -> SMEM
    for (int i = 0; i < 16; i++)
        cp16(smb + P_WI + (tid + i * 256) * 16, wab + (tid + i * 256) * 16);
    for (int i = 0; i < 16; i++)
        cp16(smb + P_WH + (tid + i * 256) * 16, wab + 131072 + (tid + i * 256) * 16);
    cp_commit(); cp_wait<0>(); __syncthreads();

    // per-fragment-row params
    const int jlo = w * 16 + (lane >> 2);
    const int jhi = jlo + 8;
    const int clo = ((jlo & 3) << 8) + rank * 32 + (jlo >> 2);
    const int chi = ((jhi & 3) << 8) + rank * 32 + (jhi >> 2);
    const float gi_lo = gih[l * G4 + clo], gi_hi = gih[l * G4 + chi];
    const float bi_lo = bih[l * G4 + clo] + bias[l * G4 + clo];
    const float bi_hi = bih[l * G4 + chi] + bias[l * G4 + chi];
    const float gh_lo = ghh[l * G4 + clo], gh_hi = ghh[l * G4 + chi];
    const float bh_lo = bhh[l * G4 + clo], bh_hi = bhh[l * G4 + chi];

    const int hc = tid >> 3, bq = tid & 7;
    const float gcv = gc[l * HH + rank * 32 + hc];
    const float bcv = bc[l * HH + rank * 32 + hc];

    float* sg = (float*)(sm + P_SG);
    char* hst = sm + P_SG;   // alias (h staging after sG reads done)

    char* myring = (char*)d_hB + (size_t)l * DD * 131072;
    const char* xring = (l == 0) ? (const char*)d_xB
                                 : (const char*)d_hB + (size_t)(l - 1) * DD * 131072;

    float cr[16];
#pragma unroll
    for (int i = 0; i < 16; i++) cr[i] = 0.f;

    for (int t = 0; t < TT; t++) {
        if (tid == 0) {
            if (l < LL - 1 && t >= DD)
                while (ld_acq(&d_cnt[l + 2]) < (unsigned)(GRP * (t - DD + 1))) {}
            if (t > 0)
                while (ld_acq(&d_cnt[l + 1]) < (unsigned)(GRP * t)) {}
            if (l > 0)
                while (ld_acq(&d_cnt[l]) < (unsigned)(GRP * (t + 1))) {}
        }
        __syncthreads();

        const char* xb = xring + (size_t)((l == 0) ? t : (t & 7)) * 131072;
        const char* hb = myring + (size_t)((t - 1) & 7) * 131072;

#define STREAM(kc) do { unsigned int sb_ = smb + P_STR + ((kc) & 1) * STRB;          \
        cp16(sb_ + tid * 16,          wab + 65536  + (kc) * 4096 + tid * 16);        \
        cp16(sb_ + 4096  + tid * 16,  wab + 196608 + (kc) * 4096 + tid * 16);        \
        cp16(sb_ + 8192  + tid * 16,  xb + (kc) * 4096 + tid * 16);                  \
        cp16(sb_ + 12288 + tid * 16,  xb + 65536 + (kc) * 4096 + tid * 16);          \
        if (t > 0) {                                                                 \
            cp16(sb_ + 16384 + tid * 16, hb + (kc) * 4096 + tid * 16);               \
            cp16(sb_ + 20480 + tid * 16, hb + 65536 + (kc) * 4096 + tid * 16);       \
        }                                                                            \
        cp_commit(); } while (0)

        float wi[64], wh[64];
#pragma unroll
        for (int i = 0; i < 64; i++) { wi[i] = 0.f; wh[i] = 0.f; }

        STREAM(0); STREAM(1);
#pragma unroll 1
        for (int kc = 0; kc < 16; kc++) {
            if (kc < 15) cp_wait<1>(); else cp_wait<0>();
            __syncthreads();
            const char* sbp = sm + P_STR + (kc & 1) * STRB;
            uint4 aWiH = *(const uint4*)(sm + P_WI + ((kc * 8 + w) * 32 + lane) * 16);
            uint4 aWhH = *(const uint4*)(sm + P_WH + ((kc * 8 + w) * 32 + lane) * 16);
            uint4 aWiL = *(const uint4*)(sbp + (w * 32 + lane) * 16);
            uint4 aWhL = *(const uint4*)(sbp + 4096 + (w * 32 + lane) * 16);
            bool doWi = (l > 0) || (kc < 5);
#pragma unroll
            for (int nb = 0; nb < 16; nb++) {
                if (doWi) {
                    uint2 bXH = *(const uint2*)(sbp + 8192 + (nb * 32 + lane) * 8);
                    uint2 bXL = *(const uint2*)(sbp + 12288 + (nb * 32 + lane) * 8);
                    mma16816(wi + nb * 4, &aWiH.x, &bXH.x);
                    mma16816(wi + nb * 4, &aWiH.x, &bXL.x);
                    mma16816(wi + nb * 4, &aWiL.x, &bXH.x);
                }
                if (t > 0) {
                    uint2 bHH = *(const uint2*)(sbp + 16384 + (nb * 32 + lane) * 8);
                    uint2 bHL = *(const uint2*)(sbp + 20480 + (nb * 32 + lane) * 8);
                    mma16816(wh + nb * 4, &aWhH.x, &bHH.x);
                    mma16816(wh + nb * 4, &aWhH.x, &bHL.x);
                    mma16816(wh + nb * 4, &aWhL.x, &bHH.x);
                }
            }
            __syncthreads();
            if (kc < 14) STREAM(kc + 2);
        }
#undef STREAM

        // ---- BN stats from fragments (row sums over batch) ----
        float sl = 0, ql = 0, sh = 0, qh = 0;   // wi side, rows lo/hi
        float tl = 0, rl = 0, th = 0, rh = 0;   // wh side
#pragma unroll
        for (int nb = 0; nb < 16; nb++) {
            sl += wi[nb*4+0] + wi[nb*4+1];
            ql += wi[nb*4+0]*wi[nb*4+0] + wi[nb*4+1]*wi[nb*4+1];
            sh += wi[nb*4+2] + wi[nb*4+3];
            qh += wi[nb*4+2]*wi[nb*4+2] + wi[nb*4+3]*wi[nb*4+3];
            tl += wh[nb*4+0] + wh[nb*4+1];
            rl += wh[nb*4+0]*wh[nb*4+0] + wh[nb*4+1]*wh[nb*4+1];
            th += wh[nb*4+2] + wh[nb*4+3];
            rh += wh[nb*4+2]*wh[nb*4+2] + wh[nb*4+3]*wh[nb*4+3];
        }
#pragma unroll
        for (int o = 1; o <= 2; o <<= 1) {
            sl += __shfl_xor_sync(0xffffffffu, sl, o);
            ql += __shfl_xor_sync(0xffffffffu, ql, o);
            sh += __shfl_xor_sync(0xffffffffu, sh, o);
            qh += __shfl_xor_sync(0xffffffffu, qh, o);
            tl += __shfl_xor_sync(0xffffffffu, tl, o);
            rl += __shfl_xor_sync(0xffffffffu, rl, o);
            th += __shfl_xor_sync(0xffffffffu, th, o);
            rh += __shfl_xor_sync(0xffffffffu, rh, o);
        }
        float ai_lo, ai_hi, ah_lo, ah_hi, bs_lo, bs_hi;
        {
            float m = sl * (1.f/128.f);
            ai_lo = gi_lo * rsqrtf(ql * (1.f/128.f) - m * m + EPSV);
            bs_lo = bi_lo - m * ai_lo;
            m = sh * (1.f/128.f);
            ai_hi = gi_hi * rsqrtf(qh * (1.f/128.f) - m * m + EPSV);
            bs_hi = bi_hi - m * ai_hi;
            if (t > 0) {
                m = tl * (1.f/128.f);
                ah_lo = gh_lo * rsqrtf(rl * (1.f/128.f) - m * m + EPSV);
                bs_lo += bh_lo - m * ah_lo;
                m = th * (1.f/128.f);
                ah_hi = gh_hi * rsqrtf(rh * (1.f/128.f) - m * m + EPSV);
                bs_hi += bh_hi - m * ah_hi;
            } else {
                ah_lo = 0.f; ah_hi = 0.f;
                bs_lo += bh_lo; bs_hi += bh_hi;
            }
        }

        // ---- two batch-half passes: s -> SMEM -> gates ----
        float og[16];
#pragma unroll 1
        for (int p = 0; p < 2; p++) {
            __syncthreads();
            const int bb0 = 2 * (lane & 3);
            const int jl = w * 16 + (lane >> 2);
#pragma unroll
            for (int nb2 = 0; nb2 < 8; nb2++) {
                int nb = p * 8 + nb2;
                int bb = nb2 * 8 + bb0;
                sg[(bb+0) * 132 + jl]     = ai_lo * wi[nb*4+0] + ah_lo * wh[nb*4+0] + bs_lo;
                sg[(bb+1) * 132 + jl]     = ai_lo * wi[nb*4+1] + ah_lo * wh[nb*4+1] + bs_lo;
                sg[(bb+0) * 132 + jl + 8] = ai_hi * wi[nb*4+2] + ah_hi * wh[nb*4+2] + bs_hi;
                sg[(bb+1) * 132 + jl + 8] = ai_hi * wi[nb*4+3] + ah_hi * wh[nb*4+3] + bs_hi;
            }
            __syncthreads();
#pragma unroll
            for (int q = 0; q < 8; q++) {
                int i = p * 8 + q;
                float4 sv = *(const float4*)&sg[(q * 8 + bq) * 132 + hc * 4];
                float fg = sigm(sv.x), ig = sigm(sv.y);
                og[i] = sigm(sv.z);
                cr[i] = fg * cr[i] + ig * tanhf(sv.w);
            }
        }

        // ---- BN(c) over batch ----
        float cs = 0.f, cq = 0.f;
#pragma unroll
        for (int i = 0; i < 16; i++) { cs += cr[i]; cq += cr[i] * cr[i]; }
#pragma unroll
        for (int o = 1; o <= 4; o <<= 1) {
            cs += __shfl_xor_sync(0xffffffffu, cs, o);
            cq += __shfl_xor_sync(0xffffffffu, cq, o);
        }
        float mc = cs * (1.f/128.f);
        float vc = cq * (1.f/128.f) - mc * mc;
        float rc = rsqrtf(vc + EPSV);
        float ac = gcv * rc, bc_ = bcv - mc * ac;
        __syncthreads();   // sG reads done -> reuse as h staging

        // ---- h, bf16 hi/lo, stage in fragment layout ----
#pragma unroll
        for (int i = 0; i < 16; i++) {
            float h = og[i] * tanhf(ac * cr[i] + bc_);
            __nv_bfloat16 hhi = __float2bfloat16(h);
            __nv_bfloat16 hlo = __float2bfloat16(h - __bfloat162float(hhi));
            int off = ((hc >> 4) * 4096)
                    + ((i * 32 + bq * 4 + ((hc & 7) >> 1)) * 8)
                    + (((hc >> 3) & 1) * 4) + ((hc & 1) * 2);
            *(__nv_bfloat16*)(hst + off) = hhi;
            *(__nv_bfloat16*)(hst + 8192 + off) = hlo;
        }
        __syncthreads();
        {
            char* slot = myring + (size_t)(t & 7) * 131072;
#pragma unroll
            for (int it = 0; it < 4; it++) {
                int idx = it * 256 + tid;
                int part = idx >> 9, r = idx & 511;
                int kbl = r >> 8, rest = r & 255;
                *(uint4*)(slot + part * 65536 + (rank * 2 + kbl) * 4096 + rest * 16)
                    = *(const uint4*)(hst + part * 8192 + kbl * 4096 + rest * 16);
            }
        }
        __threadfence();
        __syncthreads();
        if (tid == 0) arrive_rel(&d_cnt[l + 1]);
    }
}

// ================= final head =================
__launch_bounds__(256) __global__ void final_kernel(
    const float* __restrict__ Wlin, const float* __restrict__ blin,
    float* __restrict__ out)
{
    __shared__ float xr[256];
    __shared__ float lg[CC];
    __shared__ float rbuf[8];
    const char* img = (const char*)d_hB
        + (size_t)((LL - 1) * DD + ((TT - 1) & 7)) * 131072;
    int tid = threadIdx.x, warp = tid >> 5, lane = tid & 31;
    int b = blockIdx.x;
    {
        int off = boff(tid, b);
        float hi = __bfloat162float(*(const __nv_bfloat16*)(img + off));
        float lo = __bfloat162float(*(const __nv_bfloat16*)(img + 65536 + off));
        xr[tid] = hi + lo;
    }
    __syncthreads();

    float lmax = -1e30f;
    for (int cidx = tid; cidx < CC; cidx += 256) {
        float a = blin[cidx];
#pragma unroll 4
        for (int k = 0; k < 256; k++) a += xr[k] * Wlin[k * CC + cidx];
        lg[cidx] = a;
        lmax = fmaxf(lmax, a);
    }
#pragma unroll
    for (int o = 16; o; o >>= 1) lmax = fmaxf(lmax, __shfl_xor_sync(0xffffffffu, lmax, o));
    if (lane == 0) rbuf[warp] = lmax;
    __syncthreads();
    float M = rbuf[0];
#pragma unroll
    for (int w2 = 1; w2 < 8; w2++) M = fmaxf(M, rbuf[w2]);
    __syncthreads();
    float lsum = 0.f;
    for (int cidx = tid; cidx < CC; cidx += 256) {
        float e = __expf(lg[cidx] - M);
        lg[cidx] = e;
        lsum += e;
    }
#pragma unroll
    for (int o = 16; o; o >>= 1) lsum += __shfl_xor_sync(0xffffffffu, lsum, o);
    if (lane == 0) rbuf[warp] = lsum;
    __syncthreads();
    float S = 0.f;
#pragma unroll
    for (int w2 = 0; w2 < 8; w2++) S += rbuf[w2];
    float inv = 1.f / S;
    for (int cidx = tid; cidx < CC; cidx += 256)
        out[b * CC + cidx] = lg[cidx] * inv;
}

// ================= launch =================
extern "C" void kernel_launch(void* const* d_in, const int* in_sizes, int n_in,
                              void* d_out, int out_size)
{
    const float* seq  = (const float*)d_in[0];
    const float* Wih0 = (const float*)d_in[1];
    const float* Wih  = (const float*)d_in[2];
    const float* Whh  = (const float*)d_in[3];
    const float* bias = (const float*)d_in[4];
    const float* gih  = (const float*)d_in[5];
    const float* bih  = (const float*)d_in[6];
    const float* ghh  = (const float*)d_in[7];
    const float* bhh  = (const float*)d_in[8];
    const float* gc   = (const float*)d_in[9];
    const float* bc   = (const float*)d_in[10];
    const float* Wlin = (const float*)d_in[11];
    const float* blin = (const float*)d_in[12];
    float* out = (float*)d_out;

    cudaFuncSetAttribute((const void*)wave_kernel,
                         cudaFuncAttributeMaxDynamicSharedMemorySize, SMEM_TOT);

    prep_reset<<<1, 32>>>();
    prep_xseq<<<TT, 256>>>(seq);
    prep_w<<<dim3(LL, GRP), 256>>>(Wih0, Wih, Whh);
    wave_kernel<<<LL * GRP, 256, SMEM_TOT>>>(gih, bih, ghh, bhh, bias, gc, bc);
    final_kernel<<<BB, 256>>>(Wlin, blin, out);
}

// round 11
// speedup vs baseline: 1.9034x; 1.0703x over previous
#include <cuda_runtime.h>
#include <cuda_bf16.h>

#define BB 128
#define TT 152
#define II 75
#define HH 256
#define LL 16
#define CC 625
#define G4 1024
#define EPSV 1e-5f
#define DD 8
#define GRP 8

// ---------------- device scratch (no allocation allowed) ----------------
// Weights per (l,rank): 256KB = [wi_hi | wi_lo | wh_hi | wh_lo], each 64KB
// section layout (A-fragment direct): [kblk16][warpM8][lane32][16B]
__device__ __align__(128) __nv_bfloat16 d_WA[(size_t)LL * GRP * 131072];
// x / h images (B-fragment direct): per t/slot 128KB = [part2][kblk16][nblk16][lane32][8B]
__device__ __align__(128) __nv_bfloat16 d_xB[(size_t)TT * 65536];
__device__ __align__(128) __nv_bfloat16 d_hB[(size_t)LL * DD * 65536];
__device__ unsigned int d_cnt[LL + 1];

__device__ __forceinline__ float sigm(float x) { return 1.f / (1.f + __expf(-x)); }

__device__ __forceinline__ unsigned int ld_acq(const unsigned int* p) {
    unsigned int v;
    asm volatile("ld.global.acquire.gpu.u32 %0, [%1];" : "=r"(v) : "l"(p));
    return v;
}
__device__ __forceinline__ void arrive_rel(unsigned int* p) {
    asm volatile("red.release.gpu.global.add.u32 [%0], 1;" :: "l"(p) : "memory");
}
__device__ __forceinline__ void cp16(unsigned int sa, const void* g) {
    asm volatile("cp.async.cg.shared.global [%0], [%1], 16;" :: "r"(sa), "l"(g));
}
__device__ __forceinline__ void cp_commit() { asm volatile("cp.async.commit_group;"); }
template <int N>
__device__ __forceinline__ void cp_wait() { asm volatile("cp.async.wait_group %0;" :: "n"(N)); }

__device__ __forceinline__ unsigned int smem_u32(const void* p) {
    unsigned int a;
    asm("{ .reg .u64 t; cvta.to.shared.u64 t, %1; cvt.u32.u64 %0, t; }" : "=r"(a) : "l"(p));
    return a;
}

// classic warp MMA: D(m16n8 f32) += A(m16k16 bf16,row) * B(k16n8 bf16,col)
__device__ __forceinline__ void mma16816(float* d, const unsigned* a, const unsigned* b) {
    asm volatile(
        "mma.sync.aligned.m16n8k16.row.col.f32.bf16.bf16.f32 "
        "{%0,%1,%2,%3}, {%4,%5,%6,%7}, {%8,%9}, {%0,%1,%2,%3};"
        : "+f"(d[0]), "+f"(d[1]), "+f"(d[2]), "+f"(d[3])
        : "r"(a[0]), "r"(a[1]), "r"(a[2]), "r"(a[3]), "r"(b[0]), "r"(b[1]));
}

// ================= pre-pass =================
__global__ void prep_reset() {
    int i = threadIdx.x;
    if (i <= LL) d_cnt[i] = (i == 0) ? 0x40000000u : 0u;
}

// B-fragment byte offset for element (k, b) within one 64KB part image
__host__ __device__ __forceinline__ int boff(int k, int b) {
    return (((k >> 4) * 16 + (b >> 3)) * 32 + (b & 7) * 4 + ((k & 7) >> 1)) * 8
           + ((k >> 3) & 1) * 4 + (k & 1) * 2;
}
// A-fragment byte offset for element (j, k) within one 64KB section
__device__ __forceinline__ int aoff(int j, int k) {
    return (((k >> 4) * 8 + (j >> 4)) * 32 + (j & 7) * 4 + ((k & 7) >> 1)) * 16
           + (((j >> 3) & 1) + 2 * ((k >> 3) & 1)) * 4 + (k & 1) * 2;
}

__global__ void prep_xseq(const float* __restrict__ seq) {
    int t = blockIdx.x, tid = threadIdx.x;
    char* base = (char*)(d_xB + (size_t)t * 65536);
    for (int idx = tid; idx < 32768; idx += 256) {
        int b = idx >> 8, k = idx & 255;
        float v = (k < II) ? seq[(b * TT + t) * II + k] : 0.f;
        __nv_bfloat16 hi = __float2bfloat16(v);
        __nv_bfloat16 lo = __float2bfloat16(v - __bfloat162float(hi));
        int off = boff(k, b);
        *(__nv_bfloat16*)(base + off) = hi;
        *(__nv_bfloat16*)(base + 65536 + off) = lo;
    }
}

__global__ void prep_w(const float* __restrict__ Wih0, const float* __restrict__ Wih,
                       const float* __restrict__ Whh) {
    int l = blockIdx.x, rank = blockIdx.y, tid = threadIdx.x;
    char* base = (char*)d_WA + (size_t)(l * GRP + rank) * 262144;
    for (int idx = tid; idx < 32768; idx += 256) {
        int j = idx >> 8, k = idx & 255;
        int col = ((j & 3) << 8) + rank * 32 + (j >> 2);
        float vi;
        if (l == 0) vi = (k < II) ? Wih0[k * G4 + col] : 0.f;
        else        vi = Wih[((size_t)(l - 1) * HH + k) * G4 + col];
        float vh = Whh[((size_t)l * HH + k) * G4 + col];
        int off = aoff(j, k);
        __nv_bfloat16 h1 = __float2bfloat16(vi);
        *(__nv_bfloat16*)(base + off) = h1;
        *(__nv_bfloat16*)(base + 65536 + off) = __float2bfloat16(vi - __bfloat162float(h1));
        __nv_bfloat16 h2 = __float2bfloat16(vh);
        *(__nv_bfloat16*)(base + 131072 + off) = h2;
        *(__nv_bfloat16*)(base + 196608 + off) = __float2bfloat16(vh - __bfloat162float(h2));
    }
}

// ================= wavefront kernel =================
#define P_WI 0
#define P_WH 65536
#define P_STR 131072
#define STRB 24576
#define P_SG P_STR          // epilogue aliases the stream buffers (drained by then)
#define SMEM_TOT (P_STR + 3 * STRB)   // 204800

__launch_bounds__(256, 1) __global__ void wave_kernel(
    const float* __restrict__ gih, const float* __restrict__ bih,
    const float* __restrict__ ghh, const float* __restrict__ bhh,
    const float* __restrict__ bias,
    const float* __restrict__ gc,  const float* __restrict__ bc)
{
    extern __shared__ char sm[];
    const unsigned int smb = smem_u32(sm);
    const int tid = threadIdx.x, lane = tid & 31, w = tid >> 5;
    const int l = blockIdx.x >> 3, rank = blockIdx.x & 7;

    const char* wab = (const char*)d_WA + (size_t)(l * GRP + rank) * 262144;
    // persistent hi-part weights -> SMEM
    for (int i = 0; i < 16; i++)
        cp16(smb + P_WI + (tid + i * 256) * 16, wab + (tid + i * 256) * 16);
    for (int i = 0; i < 16; i++)
        cp16(smb + P_WH + (tid + i * 256) * 16, wab + 131072 + (tid + i * 256) * 16);
    cp_commit(); cp_wait<0>(); __syncthreads();

    // per-fragment-row params
    const int jlo = w * 16 + (lane >> 2);
    const int jhi = jlo + 8;
    const int clo = ((jlo & 3) << 8) + rank * 32 + (jlo >> 2);
    const int chi = ((jhi & 3) << 8) + rank * 32 + (jhi >> 2);
    const float gi_lo = gih[l * G4 + clo], gi_hi = gih[l * G4 + chi];
    const float bi_lo = bih[l * G4 + clo] + bias[l * G4 + clo];
    const float bi_hi = bih[l * G4 + chi] + bias[l * G4 + chi];
    const float gh_lo = ghh[l * G4 + clo], gh_hi = ghh[l * G4 + chi];
    const float bh_lo = bhh[l * G4 + clo], bh_hi = bhh[l * G4 + chi];

    const int hc = tid >> 3, bq = tid & 7;
    const float gcv = gc[l * HH + rank * 32 + hc];
    const float bcv = bc[l * HH + rank * 32 + hc];

    float* sg = (float*)(sm + P_SG);
    char* hst = sm + P_SG;   // alias (h staging after sG reads done)

    char* myring = (char*)d_hB + (size_t)l * DD * 131072;
    const char* xring = (l == 0) ? (const char*)d_xB
                                 : (const char*)d_hB + (size_t)(l - 1) * DD * 131072;

    float cr[16];
#pragma unroll
    for (int i = 0; i < 16; i++) cr[i] = 0.f;

    for (int t = 0; t < TT; t++) {
        // parallel step-start waits (3 independent L2 round trips)
        if (tid == 0 && l < LL - 1 && t >= DD)
            while (ld_acq(&d_cnt[l + 2]) < (unsigned)(GRP * (t - DD + 1))) {}
        if (tid == 1 && t > 0)
            while (ld_acq(&d_cnt[l + 1]) < (unsigned)(GRP * t)) {}
        if (tid == 2 && l > 0)
            while (ld_acq(&d_cnt[l]) < (unsigned)(GRP * (t + 1))) {}
        __syncthreads();

        const char* xb = xring + (size_t)((l == 0) ? t : (t & 7)) * 131072;
        const char* hb = myring + (size_t)((t - 1) & 7) * 131072;

#define STREAM(kc) do { unsigned int sb_ = smb + P_STR + ((kc) % 3) * STRB;          \
        cp16(sb_ + tid * 16,          wab + 65536  + (kc) * 4096 + tid * 16);        \
        cp16(sb_ + 4096  + tid * 16,  wab + 196608 + (kc) * 4096 + tid * 16);        \
        cp16(sb_ + 8192  + tid * 16,  xb + (kc) * 4096 + tid * 16);                  \
        cp16(sb_ + 12288 + tid * 16,  xb + 65536 + (kc) * 4096 + tid * 16);          \
        if (t > 0) {                                                                 \
            cp16(sb_ + 16384 + tid * 16, hb + (kc) * 4096 + tid * 16);               \
            cp16(sb_ + 20480 + tid * 16, hb + 65536 + (kc) * 4096 + tid * 16);       \
        }                                                                            \
        cp_commit(); } while (0)

        float wi[64], wh[64];
#pragma unroll
        for (int i = 0; i < 64; i++) { wi[i] = 0.f; wh[i] = 0.f; }

        STREAM(0); STREAM(1);
#pragma unroll 1
        for (int kc = 0; kc < 16; kc++) {
            if (kc < 15) cp_wait<1>(); else cp_wait<0>();
            __syncthreads();
            // prefetch 2 iterations ahead into the buffer drained at kc-1
            if (kc < 14) STREAM(kc + 2);
            const char* sbp = sm + P_STR + (kc % 3) * STRB;
            uint4 aWiH = *(const uint4*)(sm + P_WI + ((kc * 8 + w) * 32 + lane) * 16);
            uint4 aWhH = *(const uint4*)(sm + P_WH + ((kc * 8 + w) * 32 + lane) * 16);
            uint4 aWiL = *(const uint4*)(sbp + (w * 32 + lane) * 16);
            uint4 aWhL = *(const uint4*)(sbp + 4096 + (w * 32 + lane) * 16);
            bool doWi = (l > 0) || (kc < 5);
#pragma unroll
            for (int nb = 0; nb < 16; nb++) {
                if (doWi) {
                    uint2 bXH = *(const uint2*)(sbp + 8192 + (nb * 32 + lane) * 8);
                    uint2 bXL = *(const uint2*)(sbp + 12288 + (nb * 32 + lane) * 8);
                    mma16816(wi + nb * 4, &aWiH.x, &bXH.x);
                    mma16816(wi + nb * 4, &aWiH.x, &bXL.x);
                    mma16816(wi + nb * 4, &aWiL.x, &bXH.x);
                }
                if (t > 0) {
                    uint2 bHH = *(const uint2*)(sbp + 16384 + (nb * 32 + lane) * 8);
                    uint2 bHL = *(const uint2*)(sbp + 20480 + (nb * 32 + lane) * 8);
                    mma16816(wh + nb * 4, &aWhH.x, &bHH.x);
                    mma16816(wh + nb * 4, &aWhH.x, &bHL.x);
                    mma16816(wh + nb * 4, &aWhL.x, &bHH.x);
                }
            }
        }
#undef STREAM

        // ---- BN stats from fragments (row sums over batch) ----
        float sl = 0, ql = 0, sh = 0, qh = 0;   // wi side, rows lo/hi
        float tl = 0, rl = 0, th = 0, rh = 0;   // wh side
#pragma unroll
        for (int nb = 0; nb < 16; nb++) {
            sl += wi[nb*4+0] + wi[nb*4+1];
            ql += wi[nb*4+0]*wi[nb*4+0] + wi[nb*4+1]*wi[nb*4+1];
            sh += wi[nb*4+2] + wi[nb*4+3];
            qh += wi[nb*4+2]*wi[nb*4+2] + wi[nb*4+3]*wi[nb*4+3];
            tl += wh[nb*4+0] + wh[nb*4+1];
            rl += wh[nb*4+0]*wh[nb*4+0] + wh[nb*4+1]*wh[nb*4+1];
            th += wh[nb*4+2] + wh[nb*4+3];
            rh += wh[nb*4+2]*wh[nb*4+2] + wh[nb*4+3]*wh[nb*4+3];
        }
#pragma unroll
        for (int o = 1; o <= 2; o <<= 1) {
            sl += __shfl_xor_sync(0xffffffffu, sl, o);
            ql += __shfl_xor_sync(0xffffffffu, ql, o);
            sh += __shfl_xor_sync(0xffffffffu, sh, o);
            qh += __shfl_xor_sync(0xffffffffu, qh, o);
            tl += __shfl_xor_sync(0xffffffffu, tl, o);
            rl += __shfl_xor_sync(0xffffffffu, rl, o);
            th += __shfl_xor_sync(0xffffffffu, th, o);
            rh += __shfl_xor_sync(0xffffffffu, rh, o);
        }
        float ai_lo, ai_hi, ah_lo, ah_hi, bs_lo, bs_hi;
        {
            float m = sl * (1.f/128.f);
            ai_lo = gi_lo * rsqrtf(ql * (1.f/128.f) - m * m + EPSV);
            bs_lo = bi_lo - m * ai_lo;
            m = sh * (1.f/128.f);
            ai_hi = gi_hi * rsqrtf(qh * (1.f/128.f) - m * m + EPSV);
            bs_hi = bi_hi - m * ai_hi;
            if (t > 0) {
                m = tl * (1.f/128.f);
                ah_lo = gh_lo * rsqrtf(rl * (1.f/128.f) - m * m + EPSV);
                bs_lo += bh_lo - m * ah_lo;
                m = th * (1.f/128.f);
                ah_hi = gh_hi * rsqrtf(rh * (1.f/128.f) - m * m + EPSV);
                bs_hi += bh_hi - m * ah_hi;
            } else {
                ah_lo = 0.f; ah_hi = 0.f;
                bs_lo += bh_lo; bs_hi += bh_hi;
            }
        }

        // ---- two batch-half passes: s -> SMEM -> gates ----
        float og[16];
#pragma unroll 1
        for (int p = 0; p < 2; p++) {
            __syncthreads();
            const int bb0 = 2 * (lane & 3);
            const int jl = w * 16 + (lane >> 2);
#pragma unroll
            for (int nb2 = 0; nb2 < 8; nb2++) {
                int nb = p * 8 + nb2;
                int bb = nb2 * 8 + bb0;
                sg[(bb+0) * 132 + jl]     = ai_lo * wi[nb*4+0] + ah_lo * wh[nb*4+0] + bs_lo;
                sg[(bb+1) * 132 + jl]     = ai_lo * wi[nb*4+1] + ah_lo * wh[nb*4+1] + bs_lo;
                sg[(bb+0) * 132 + jl + 8] = ai_hi * wi[nb*4+2] + ah_hi * wh[nb*4+2] + bs_hi;
                sg[(bb+1) * 132 + jl + 8] = ai_hi * wi[nb*4+3] + ah_hi * wh[nb*4+3] + bs_hi;
            }
            __syncthreads();
#pragma unroll
            for (int q = 0; q < 8; q++) {
                int i = p * 8 + q;
                float4 sv = *(const float4*)&sg[(q * 8 + bq) * 132 + hc * 4];
                float fg = sigm(sv.x), ig = sigm(sv.y);
                og[i] = sigm(sv.z);
                cr[i] = fg * cr[i] + ig * tanhf(sv.w);
            }
        }

        // ---- BN(c) over batch ----
        float cs = 0.f, cq = 0.f;
#pragma unroll
        for (int i = 0; i < 16; i++) { cs += cr[i]; cq += cr[i] * cr[i]; }
#pragma unroll
        for (int o = 1; o <= 4; o <<= 1) {
            cs += __shfl_xor_sync(0xffffffffu, cs, o);
            cq += __shfl_xor_sync(0xffffffffu, cq, o);
        }
        float mc = cs * (1.f/128.f);
        float vc = cq * (1.f/128.f) - mc * mc;
        float rc = rsqrtf(vc + EPSV);
        float ac = gcv * rc, bc_ = bcv - mc * ac;
        __syncthreads();   // sG reads done -> reuse as h staging

        // ---- h, bf16 hi/lo, stage in fragment layout ----
#pragma unroll
        for (int i = 0; i < 16; i++) {
            float h = og[i] * tanhf(ac * cr[i] + bc_);
            __nv_bfloat16 hhi = __float2bfloat16(h);
            __nv_bfloat16 hlo = __float2bfloat16(h - __bfloat162float(hhi));
            int off = ((hc >> 4) * 4096)
                    + ((i * 32 + bq * 4 + ((hc & 7) >> 1)) * 8)
                    + (((hc >> 3) & 1) * 4) + ((hc & 1) * 2);
            *(__nv_bfloat16*)(hst + off) = hhi;
            *(__nv_bfloat16*)(hst + 8192 + off) = hlo;
        }
        __syncthreads();
        {
            char* slot = myring + (size_t)(t & 7) * 131072;
#pragma unroll
            for (int it = 0; it < 4; it++) {
                int idx = it * 256 + tid;
                int part = idx >> 9, r = idx & 511;
                int kbl = r >> 8, rest = r & 255;
                *(uint4*)(slot + part * 65536 + (rank * 2 + kbl) * 4096 + rest * 16)
                    = *(const uint4*)(hst + part * 8192 + kbl * 4096 + rest * 16);
            }
        }
        __threadfence();
        __syncthreads();
        if (tid == 0) arrive_rel(&d_cnt[l + 1]);
    }
}

// ================= final head =================
__launch_bounds__(256) __global__ void final_kernel(
    const float* __restrict__ Wlin, const float* __restrict__ blin,
    float* __restrict__ out)
{
    __shared__ float xr[256];
    __shared__ float lg[CC];
    __shared__ float rbuf[8];
    const char* img = (const char*)d_hB
        + (size_t)((LL - 1) * DD + ((TT - 1) & 7)) * 131072;
    int tid = threadIdx.x, warp = tid >> 5, lane = tid & 31;
    int b = blockIdx.x;
    {
        int off = boff(tid, b);
        float hi = __bfloat162float(*(const __nv_bfloat16*)(img + off));
        float lo = __bfloat162float(*(const __nv_bfloat16*)(img + 65536 + off));
        xr[tid] = hi + lo;
    }
    __syncthreads();

    float lmax = -1e30f;
    for (int cidx = tid; cidx < CC; cidx += 256) {
        float a = blin[cidx];
#pragma unroll 4
        for (int k = 0; k < 256; k++) a += xr[k] * Wlin[k * CC + cidx];
        lg[cidx] = a;
        lmax = fmaxf(lmax, a);
    }
#pragma unroll
    for (int o = 16; o; o >>= 1) lmax = fmaxf(lmax, __shfl_xor_sync(0xffffffffu, lmax, o));
    if (lane == 0) rbuf[warp] = lmax;
    __syncthreads();
    float M = rbuf[0];
#pragma unroll
    for (int w2 = 1; w2 < 8; w2++) M = fmaxf(M, rbuf[w2]);
    __syncthreads();
    float lsum = 0.f;
    for (int cidx = tid; cidx < CC; cidx += 256) {
        float e = __expf(lg[cidx] - M);
        lg[cidx] = e;
        lsum += e;
    }
#pragma unroll
    for (int o = 16; o; o >>= 1) lsum += __shfl_xor_sync(0xffffffffu, lsum, o);
    if (lane == 0) rbuf[warp] = lsum;
    __syncthreads();
    float S = 0.f;
#pragma unroll
    for (int w2 = 0; w2 < 8; w2++) S += rbuf[w2];
    float inv = 1.f / S;
    for (int cidx = tid; cidx < CC; cidx += 256)
        out[b * CC + cidx] = lg[cidx] * inv;
}

// ================= launch =================
extern "C" void kernel_launch(void* const* d_in, const int* in_sizes, int n_in,
                              void* d_out, int out_size)
{
    const float* seq  = (const float*)d_in[0];
    const float* Wih0 = (const float*)d_in[1];
    const float* Wih  = (const float*)d_in[2];
    const float* Whh  = (const float*)d_in[3];
    const float* bias = (const float*)d_in[4];
    const float* gih  = (const float*)d_in[5];
    const float* bih  = (const float*)d_in[6];
    const float* ghh  = (const float*)d_in[7];
    const float* bhh  = (const float*)d_in[8];
    const float* gc   = (const float*)d_in[9];
    const float* bc   = (const float*)d_in[10];
    const float* Wlin = (const float*)d_in[11];
    const float* blin = (const float*)d_in[12];
    float* out = (float*)d_out;

    cudaFuncSetAttribute((const void*)wave_kernel,
                         cudaFuncAttributeMaxDynamicSharedMemorySize, SMEM_TOT);

    prep_reset<<<1, 32>>>();
    prep_xseq<<<TT, 256>>>(seq);
    prep_w<<<dim3(LL, GRP), 256>>>(Wih0, Wih, Whh);
    wave_kernel<<<LL * GRP, 256, SMEM_TOT>>>(gih, bih, ghh, bhh, bias, gc, bc);
    final_kernel<<<BB, 256>>>(Wlin, blin, out);
}

// round 12
// speedup vs baseline: 3.9400x; 2.0699x over previous
#include <cuda_runtime.h>
#include <cuda_bf16.h>

#define BB 128
#define TT 152
#define II 75
#define HH 256
#define LL 16
#define CC 625
#define G4 1024
#define EPSV 1e-5f
#define DD 8
#define GRP 8

// ---------------- device scratch (no allocation allowed) ----------------
// Weights per (l,rank): 256KB = [wi_hi | wi_lo | wh_hi | wh_lo], each 64KB
// section layout (A-fragment direct): [kblk16][warpM8][lane32][16B]
__device__ __align__(128) __nv_bfloat16 d_WA[(size_t)LL * GRP * 131072];
// x / h images (B-fragment direct): per t/slot 128KB = [part2][kblk16][nblk16][lane32][8B]
__device__ __align__(128) __nv_bfloat16 d_xB[(size_t)TT * 65536];
__device__ __align__(128) __nv_bfloat16 d_hB[(size_t)LL * DD * 65536];
__device__ unsigned int d_cnt[LL + 1];

__device__ __forceinline__ float sigm(float x) { return 1.f / (1.f + __expf(-x)); }

__device__ __forceinline__ unsigned int ld_acq(const unsigned int* p) {
    unsigned int v;
    asm volatile("ld.global.acquire.gpu.u32 %0, [%1];" : "=r"(v) : "l"(p));
    return v;
}
__device__ __forceinline__ void arrive_rel(unsigned int* p) {
    asm volatile("red.release.gpu.global.add.u32 [%0], 1;" :: "l"(p) : "memory");
}
__device__ __forceinline__ void cp16(unsigned int sa, const void* g) {
    asm volatile("cp.async.cg.shared.global [%0], [%1], 16;" :: "r"(sa), "l"(g));
}
__device__ __forceinline__ void cp_commit() { asm volatile("cp.async.commit_group;"); }
template <int N>
__device__ __forceinline__ void cp_wait() { asm volatile("cp.async.wait_group %0;" :: "n"(N)); }

__device__ __forceinline__ unsigned int smem_u32(const void* p) {
    unsigned int a;
    asm("{ .reg .u64 t; cvta.to.shared.u64 t, %1; cvt.u32.u64 %0, t; }" : "=r"(a) : "l"(p));
    return a;
}

// classic warp MMA: D(m16n8 f32) += A(m16k16 bf16,row) * B(k16n8 bf16,col)
__device__ __forceinline__ void mma16816(float* d, const unsigned* a, const unsigned* b) {
    asm volatile(
        "mma.sync.aligned.m16n8k16.row.col.f32.bf16.bf16.f32 "
        "{%0,%1,%2,%3}, {%4,%5,%6,%7}, {%8,%9}, {%0,%1,%2,%3};"
        : "+f"(d[0]), "+f"(d[1]), "+f"(d[2]), "+f"(d[3])
        : "r"(a[0]), "r"(a[1]), "r"(a[2]), "r"(a[3]), "r"(b[0]), "r"(b[1]));
}

// ================= pre-pass =================
__global__ void prep_reset() {
    int i = threadIdx.x;
    if (i <= LL) d_cnt[i] = (i == 0) ? 0x40000000u : 0u;
}

// B-fragment byte offset for element (k, b) within one 64KB part image
__host__ __device__ __forceinline__ int boff(int k, int b) {
    return (((k >> 4) * 16 + (b >> 3)) * 32 + (b & 7) * 4 + ((k & 7) >> 1)) * 8
           + ((k >> 3) & 1) * 4 + (k & 1) * 2;
}
// A-fragment byte offset for element (j, k) within one 64KB section
__device__ __forceinline__ int aoff(int j, int k) {
    return (((k >> 4) * 8 + (j >> 4)) * 32 + (j & 7) * 4 + ((k & 7) >> 1)) * 16
           + (((j >> 3) & 1) + 2 * ((k >> 3) & 1)) * 4 + (k & 1) * 2;
}

__global__ void prep_xseq(const float* __restrict__ seq) {
    int t = blockIdx.x, tid = threadIdx.x;
    char* base = (char*)(d_xB + (size_t)t * 65536);
    for (int idx = tid; idx < 32768; idx += 256) {
        int b = idx >> 8, k = idx & 255;
        float v = (k < II) ? seq[(b * TT + t) * II + k] : 0.f;
        __nv_bfloat16 hi = __float2bfloat16(v);
        __nv_bfloat16 lo = __float2bfloat16(v - __bfloat162float(hi));
        int off = boff(k, b);
        *(__nv_bfloat16*)(base + off) = hi;
        *(__nv_bfloat16*)(base + 65536 + off) = lo;
    }
}

__global__ void prep_w(const float* __restrict__ Wih0, const float* __restrict__ Wih,
                       const float* __restrict__ Whh) {
    int l = blockIdx.x, rank = blockIdx.y, tid = threadIdx.x;
    char* base = (char*)d_WA + (size_t)(l * GRP + rank) * 262144;
    for (int idx = tid; idx < 32768; idx += 256) {
        int j = idx >> 8, k = idx & 255;
        int col = ((j & 3) << 8) + rank * 32 + (j >> 2);
        float vi;
        if (l == 0) vi = (k < II) ? Wih0[k * G4 + col] : 0.f;
        else        vi = Wih[((size_t)(l - 1) * HH + k) * G4 + col];
        float vh = Whh[((size_t)l * HH + k) * G4 + col];
        int off = aoff(j, k);
        __nv_bfloat16 h1 = __float2bfloat16(vi);
        *(__nv_bfloat16*)(base + off) = h1;
        *(__nv_bfloat16*)(base + 65536 + off) = __float2bfloat16(vi - __bfloat162float(h1));
        __nv_bfloat16 h2 = __float2bfloat16(vh);
        *(__nv_bfloat16*)(base + 131072 + off) = h2;
        *(__nv_bfloat16*)(base + 196608 + off) = __float2bfloat16(vh - __bfloat162float(h2));
    }
}

// ================= wavefront kernel =================
#define P_WI 0
#define P_WH 65536
#define P_STR 131072
#define STRB 24576
#define P_RED P_STR                    // 4KB, aliases drained stream buf
#define P_SG  (P_STR + 4096)           // 128*132*4 = 67584, fits 3*STRB-4096
#define P_PRM (P_STR + 3 * STRB)       // 2304B params
#define SMEM_TOT (P_PRM + 2304)        // 207104

__launch_bounds__(512, 1) __global__ void wave_kernel(
    const float* __restrict__ gih, const float* __restrict__ bih,
    const float* __restrict__ ghh, const float* __restrict__ bhh,
    const float* __restrict__ bias,
    const float* __restrict__ gc,  const float* __restrict__ bc)
{
    extern __shared__ char sm[];
    const unsigned int smb = smem_u32(sm);
    const int tid = threadIdx.x, lane = tid & 31, w = tid >> 5;
    const int wm = w & 7, wn = w >> 3;
    const int l = blockIdx.x >> 3, rank = blockIdx.x & 7;

    const char* wab = (const char*)d_WA + (size_t)(l * GRP + rank) * 262144;
    // persistent hi-part weights -> SMEM (512 threads)
    for (int i = 0; i < 8; i++)
        cp16(smb + P_WI + (tid + i * 512) * 16, wab + (tid + i * 512) * 16);
    for (int i = 0; i < 8; i++)
        cp16(smb + P_WH + (tid + i * 512) * 16, wab + 131072 + (tid + i * 512) * 16);
    cp_commit();

    // static per-column params -> SMEM
    float* prm = (float*)(sm + P_PRM);
    if (tid < 128) {
        int colg = ((tid & 3) << 8) + rank * 32 + (tid >> 2);
        prm[tid]       = gih[l * G4 + colg];
        prm[128 + tid] = bih[l * G4 + colg] + bias[l * G4 + colg];
        prm[256 + tid] = ghh[l * G4 + colg];
        prm[384 + tid] = bhh[l * G4 + colg];
    } else if (tid < 160) {
        int hcg = tid - 128;
        prm[512 + hcg] = gc[l * HH + rank * 32 + hcg];
        prm[544 + hcg] = bc[l * HH + rank * 32 + hcg];
    }
    cp_wait<0>(); __syncthreads();

    const int hc = tid >> 4, bq = tid & 15;

    float* red = (float*)(sm + P_RED);
    float* sg  = (float*)(sm + P_SG);
    char* hst  = sm + P_SG;   // alias (h staging after sg reads done)

    char* myring = (char*)d_hB + (size_t)l * DD * 131072;
    const char* xring = (l == 0) ? (const char*)d_xB
                                 : (const char*)d_hB + (size_t)(l - 1) * DD * 131072;

    float cr[8];
#pragma unroll
    for (int i = 0; i < 8; i++) cr[i] = 0.f;

    for (int t = 0; t < TT; t++) {
        // parallel step-start waits (3 independent L2 round trips)
        if (tid == 0 && l < LL - 1 && t >= DD)
            while (ld_acq(&d_cnt[l + 2]) < (unsigned)(GRP * (t - DD + 1))) {}
        if (tid == 1 && t > 0)
            while (ld_acq(&d_cnt[l + 1]) < (unsigned)(GRP * t)) {}
        if (tid == 2 && l > 0)
            while (ld_acq(&d_cnt[l]) < (unsigned)(GRP * (t + 1))) {}
        __syncthreads();

        const char* xb = xring + (size_t)((l == 0) ? t : (t & 7)) * 131072;
        const char* hb = myring + (size_t)((t - 1) & 7) * 131072;

#define STREAM(kc) do { unsigned int sb_ = smb + P_STR + ((kc) % 3) * STRB;           \
        int t2_ = tid & 255;                                                          \
        if (tid < 256) {                                                              \
            cp16(sb_ + t2_ * 16,         wab + 65536  + (kc) * 4096 + t2_ * 16);      \
            cp16(sb_ + 8192 + t2_ * 16,  xb + (kc) * 4096 + t2_ * 16);                \
            if (t > 0) cp16(sb_ + 16384 + t2_ * 16, hb + (kc) * 4096 + t2_ * 16);     \
        } else {                                                                      \
            cp16(sb_ + 4096  + t2_ * 16, wab + 196608 + (kc) * 4096 + t2_ * 16);      \
            cp16(sb_ + 12288 + t2_ * 16, xb + 65536 + (kc) * 4096 + t2_ * 16);        \
            if (t > 0) cp16(sb_ + 20480 + t2_ * 16, hb + 65536 + (kc) * 4096 + t2_ * 16); \
        }                                                                             \
        cp_commit(); } while (0)

        float wi[32], wh[32];
#pragma unroll
        for (int i = 0; i < 32; i++) { wi[i] = 0.f; wh[i] = 0.f; }

        STREAM(0); STREAM(1);
#pragma unroll 1
        for (int kc = 0; kc < 16; kc++) {
            if (kc < 15) cp_wait<1>(); else cp_wait<0>();
            __syncthreads();
            if (kc < 14) STREAM(kc + 2);
            const char* sbp = sm + P_STR + (kc % 3) * STRB;
            uint4 aWiH = *(const uint4*)(sm + P_WI + ((kc * 8 + wm) * 32 + lane) * 16);
            uint4 aWhH = *(const uint4*)(sm + P_WH + ((kc * 8 + wm) * 32 + lane) * 16);
            uint4 aWiL = *(const uint4*)(sbp + (wm * 32 + lane) * 16);
            uint4 aWhL = *(const uint4*)(sbp + 4096 + (wm * 32 + lane) * 16);
            bool doWi = (l > 0) || (kc < 5);
#pragma unroll
            for (int nb = 0; nb < 8; nb++) {
                int nblk = wn * 8 + nb;
                if (doWi) {
                    uint2 bXH = *(const uint2*)(sbp + 8192 + (nblk * 32 + lane) * 8);
                    uint2 bXL = *(const uint2*)(sbp + 12288 + (nblk * 32 + lane) * 8);
                    mma16816(wi + nb * 4, &aWiH.x, &bXH.x);
                    mma16816(wi + nb * 4, &aWiH.x, &bXL.x);
                    mma16816(wi + nb * 4, &aWiL.x, &bXH.x);
                }
                if (t > 0) {
                    uint2 bHH = *(const uint2*)(sbp + 16384 + (nblk * 32 + lane) * 8);
                    uint2 bHL = *(const uint2*)(sbp + 20480 + (nblk * 32 + lane) * 8);
                    mma16816(wh + nb * 4, &aWhH.x, &bHH.x);
                    mma16816(wh + nb * 4, &aWhH.x, &bHL.x);
                    mma16816(wh + nb * 4, &aWhL.x, &bHH.x);
                }
            }
        }
#undef STREAM

        // ---- per-warp partial BN stats over this warp's 64 batches ----
        float sl = 0, ql = 0, sh = 0, qh = 0;   // wi side, rows lo/hi
        float tl = 0, rl = 0, th = 0, rh = 0;   // wh side
#pragma unroll
        for (int nb = 0; nb < 8; nb++) {
            sl += wi[nb*4+0] + wi[nb*4+1];
            ql += wi[nb*4+0]*wi[nb*4+0] + wi[nb*4+1]*wi[nb*4+1];
            sh += wi[nb*4+2] + wi[nb*4+3];
            qh += wi[nb*4+2]*wi[nb*4+2] + wi[nb*4+3]*wi[nb*4+3];
            tl += wh[nb*4+0] + wh[nb*4+1];
            rl += wh[nb*4+0]*wh[nb*4+0] + wh[nb*4+1]*wh[nb*4+1];
            th += wh[nb*4+2] + wh[nb*4+3];
            rh += wh[nb*4+2]*wh[nb*4+2] + wh[nb*4+3]*wh[nb*4+3];
        }
#pragma unroll
        for (int o = 1; o <= 2; o <<= 1) {
            sl += __shfl_xor_sync(0xffffffffu, sl, o);
            ql += __shfl_xor_sync(0xffffffffu, ql, o);
            sh += __shfl_xor_sync(0xffffffffu, sh, o);
            qh += __shfl_xor_sync(0xffffffffu, qh, o);
            tl += __shfl_xor_sync(0xffffffffu, tl, o);
            rl += __shfl_xor_sync(0xffffffffu, rl, o);
            th += __shfl_xor_sync(0xffffffffu, th, o);
            rh += __shfl_xor_sync(0xffffffffu, rh, o);
        }
        if ((lane & 3) == 0) {
            float* rp = red + (w * 8 + (lane >> 2)) * 8;
            rp[0] = sl; rp[1] = ql; rp[2] = sh; rp[3] = qh;
            rp[4] = tl; rp[5] = rl; rp[6] = th; rp[7] = rh;
        }
        __syncthreads();

        // ---- combine halves, compute per-row BN coefficients ----
        float ai_lo, ai_hi, ah_lo, ah_hi, bs_lo, bs_hi;
        {
            int r = lane >> 2;
            const float* rp0 = red + ((wm)     * 8 + r) * 8;
            const float* rp1 = red + ((wm + 8) * 8 + r) * 8;
            float Sl = rp0[0] + rp1[0], Ql = rp0[1] + rp1[1];
            float Sh = rp0[2] + rp1[2], Qh = rp0[3] + rp1[3];
            float Tl = rp0[4] + rp1[4], Rl = rp0[5] + rp1[5];
            float Th = rp0[6] + rp1[6], Rh = rp0[7] + rp1[7];
            int jlo = wm * 16 + r, jhi = jlo + 8;
            float m = Sl * (1.f/128.f);
            ai_lo = prm[jlo] * rsqrtf(Ql * (1.f/128.f) - m * m + EPSV);
            bs_lo = prm[128 + jlo] - m * ai_lo;
            m = Sh * (1.f/128.f);
            ai_hi = prm[jhi] * rsqrtf(Qh * (1.f/128.f) - m * m + EPSV);
            bs_hi = prm[128 + jhi] - m * ai_hi;
            if (t > 0) {
                m = Tl * (1.f/128.f);
                ah_lo = prm[256 + jlo] * rsqrtf(Rl * (1.f/128.f) - m * m + EPSV);
                bs_lo += prm[384 + jlo] - m * ah_lo;
                m = Th * (1.f/128.f);
                ah_hi = prm[256 + jhi] * rsqrtf(Rh * (1.f/128.f) - m * m + EPSV);
                bs_hi += prm[384 + jhi] - m * ah_hi;
            } else {
                ah_lo = 0.f; ah_hi = 0.f;
                bs_lo += prm[384 + jlo]; bs_hi += prm[384 + jhi];
            }
        }

        // ---- single pass: s -> SMEM (all 128 batches at once) ----
        {
            const int c2 = 2 * (lane & 3);
            const int jl = wm * 16 + (lane >> 2);
#pragma unroll
            for (int nb = 0; nb < 8; nb++) {
                int bb = wn * 64 + nb * 8 + c2;
                sg[(bb+0) * 132 + jl]     = ai_lo * wi[nb*4+0] + ah_lo * wh[nb*4+0] + bs_lo;
                sg[(bb+1) * 132 + jl]     = ai_lo * wi[nb*4+1] + ah_lo * wh[nb*4+1] + bs_lo;
                sg[(bb+0) * 132 + jl + 8] = ai_hi * wi[nb*4+2] + ah_hi * wh[nb*4+2] + bs_hi;
                sg[(bb+1) * 132 + jl + 8] = ai_hi * wi[nb*4+3] + ah_hi * wh[nb*4+3] + bs_hi;
            }
        }
        __syncthreads();

        // ---- gates: thread (hc 0..31, bq 0..15) handles 8 batches ----
        float og[8];
#pragma unroll
        for (int i = 0; i < 8; i++) {
            float4 sv = *(const float4*)&sg[(i * 16 + bq) * 132 + hc * 4];
            float fg = sigm(sv.x), ig = sigm(sv.y);
            og[i] = sigm(sv.z);
            cr[i] = fg * cr[i] + ig * tanhf(sv.w);
        }

        // ---- BN(c) over batch (16-lane groups share hc) ----
        float cs = 0.f, cq = 0.f;
#pragma unroll
        for (int i = 0; i < 8; i++) { cs += cr[i]; cq += cr[i] * cr[i]; }
#pragma unroll
        for (int o = 1; o <= 8; o <<= 1) {
            cs += __shfl_xor_sync(0xffffffffu, cs, o);
            cq += __shfl_xor_sync(0xffffffffu, cq, o);
        }
        float mc = cs * (1.f/128.f);
        float vc = cq * (1.f/128.f) - mc * mc;
        float rc = rsqrtf(vc + EPSV);
        float ac = prm[512 + hc] * rc, bc_ = prm[544 + hc] - mc * ac;
        __syncthreads();   // sg reads done -> reuse as h staging

        // ---- h, bf16 hi/lo, stage in fragment layout ----
#pragma unroll
        for (int i = 0; i < 8; i++) {
            float h = og[i] * tanhf(ac * cr[i] + bc_);
            __nv_bfloat16 hhi = __float2bfloat16(h);
            __nv_bfloat16 hlo = __float2bfloat16(h - __bfloat162float(hhi));
            int off = ((hc >> 4) * 4096)
                    + ((2 * i + (bq >> 3)) * 256)
                    + ((bq & 7) * 32) + (((hc & 7) >> 1) * 8)
                    + (((hc >> 3) & 1) * 4) + ((hc & 1) * 2);
            *(__nv_bfloat16*)(hst + off) = hhi;
            *(__nv_bfloat16*)(hst + 8192 + off) = hlo;
        }
        __syncthreads();
        {
            char* slot = myring + (size_t)(t & 7) * 131072;
#pragma unroll
            for (int it = 0; it < 2; it++) {
                int idx = it * 512 + tid;
                int part = idx >> 9, r = idx & 511;
                int kbl = r >> 8, rest = r & 255;
                *(uint4*)(slot + part * 65536 + (rank * 2 + kbl) * 4096 + rest * 16)
                    = *(const uint4*)(hst + part * 8192 + kbl * 4096 + rest * 16);
            }
        }
        __threadfence();
        __syncthreads();
        if (tid == 0) arrive_rel(&d_cnt[l + 1]);
    }
}

// ================= final head =================
__launch_bounds__(256) __global__ void final_kernel(
    const float* __restrict__ Wlin, const float* __restrict__ blin,
    float* __restrict__ out)
{
    __shared__ float xr[256];
    __shared__ float lg[CC];
    __shared__ float rbuf[8];
    const char* img = (const char*)d_hB
        + (size_t)((LL - 1) * DD + ((TT - 1) & 7)) * 131072;
    int tid = threadIdx.x, warp = tid >> 5, lane = tid & 31;
    int b = blockIdx.x;
    {
        int off = boff(tid, b);
        float hi = __bfloat162float(*(const __nv_bfloat16*)(img + off));
        float lo = __bfloat162float(*(const __nv_bfloat16*)(img + 65536 + off));
        xr[tid] = hi + lo;
    }
    __syncthreads();

    float lmax = -1e30f;
    for (int cidx = tid; cidx < CC; cidx += 256) {
        float a = blin[cidx];
#pragma unroll 4
        for (int k = 0; k < 256; k++) a += xr[k] * Wlin[k * CC + cidx];
        lg[cidx] = a;
        lmax = fmaxf(lmax, a);
    }
#pragma unroll
    for (int o = 16; o; o >>= 1) lmax = fmaxf(lmax, __shfl_xor_sync(0xffffffffu, lmax, o));
    if (lane == 0) rbuf[warp] = lmax;
    __syncthreads();
    float M = rbuf[0];
#pragma unroll
    for (int w2 = 1; w2 < 8; w2++) M = fmaxf(M, rbuf[w2]);
    __syncthreads();
    float lsum = 0.f;
    for (int cidx = tid; cidx < CC; cidx += 256) {
        float e = __expf(lg[cidx] - M);
        lg[cidx] = e;
        lsum += e;
    }
#pragma unroll
    for (int o = 16; o; o >>= 1) lsum += __shfl_xor_sync(0xffffffffu, lsum, o);
    if (lane == 0) rbuf[warp] = lsum;
    __syncthreads();
    float S = 0.f;
#pragma unroll
    for (int w2 = 0; w2 < 8; w2++) S += rbuf[w2];
    float inv = 1.f / S;
    for (int cidx = tid; cidx < CC; cidx += 256)
        out[b * CC + cidx] = lg[cidx] * inv;
}

// ================= launch =================
extern "C" void kernel_launch(void* const* d_in, const int* in_sizes, int n_in,
                              void* d_out, int out_size)
{
    const float* seq  = (const float*)d_in[0];
    const float* Wih0 = (const float*)d_in[1];
    const float* Wih  = (const float*)d_in[2];
    const float* Whh  = (const float*)d_in[3];
    const float* bias = (const float*)d_in[4];
    const float* gih  = (const float*)d_in[5];
    const float* bih  = (const float*)d_in[6];
    const float* ghh  = (const float*)d_in[7];
    const float* bhh  = (const float*)d_in[8];
    const float* gc   = (const float*)d_in[9];
    const float* bc   = (const float*)d_in[10];
    const float* Wlin = (const float*)d_in[11];
    const float* blin = (const float*)d_in[12];
    float* out = (float*)d_out;

    cudaFuncSetAttribute((const void*)wave_kernel,
                         cudaFuncAttributeMaxDynamicSharedMemorySize, SMEM_TOT);

    prep_reset<<<1, 32>>>();
    prep_xseq<<<TT, 256>>>(seq);
    prep_w<<<dim3(LL, GRP), 256>>>(Wih0, Wih, Whh);
    wave_kernel<<<LL * GRP, 512, SMEM_TOT>>>(gih, bih, ghh, bhh, bias, gc, bc);
    final_kernel<<<BB, 256>>>(Wlin, blin, out);
}